// round 1
// baseline (speedup 1.0000x reference)
#include <cuda_runtime.h>

#define T_STEPS 256
#define BATCH   128
#define DHDIM   512
#define LDIM    3
#define KDIM    (DHDIM * LDIM)   // 1536
#define K4      (KDIM / 4)       // 384

// Scratch for precomputed input projections: X[t*BATCH + b] = (Xc, Xh)
__device__ float2 g_X[T_STEPS * BATCH];

// ---------------------------------------------------------------------------
// Pass 1: X[t,b,o] = sum_k inputs[t,b,k] * Wi[o,k] + bi[o]
// One warp per (t,b) pair; each block handles 32 pairs with Wi cached in SMEM.
// HBM-bound: streams the full 201MB input tensor once.
// ---------------------------------------------------------------------------
__global__ void __launch_bounds__(256) precompute_x_kernel(
    const float* __restrict__ in,
    const float* __restrict__ Wi,
    const float* __restrict__ bi)
{
    __shared__ float4 sW0[K4];
    __shared__ float4 sW1[K4];
    const int tid = threadIdx.x;
    const float4* Wi4 = reinterpret_cast<const float4*>(Wi);
    for (int i = tid; i < K4; i += 256) {
        sW0[i] = Wi4[i];
        sW1[i] = Wi4[K4 + i];
    }
    __syncthreads();

    const int warp = tid >> 5;
    const int lane = tid & 31;
    const float bi0 = __ldg(bi);
    const float bi1 = __ldg(bi + 1);
    const float4* in4 = reinterpret_cast<const float4*>(in);

    #pragma unroll
    for (int r = 0; r < 4; r++) {
        const int p = blockIdx.x * 32 + r * 8 + warp;  // p = t*BATCH + b
        float a0 = 0.0f, a1 = 0.0f;
        const long base = (long)p * K4;
        #pragma unroll
        for (int i = 0; i < 12; i++) {
            float4 v  = in4[base + i * 32 + lane];
            float4 w0 = sW0[i * 32 + lane];
            float4 w1 = sW1[i * 32 + lane];
            a0 = fmaf(v.x, w0.x, fmaf(v.y, w0.y, fmaf(v.z, w0.z, fmaf(v.w, w0.w, a0))));
            a1 = fmaf(v.x, w1.x, fmaf(v.y, w1.y, fmaf(v.z, w1.z, fmaf(v.w, w1.w, a1))));
        }
        #pragma unroll
        for (int o = 16; o; o >>= 1) {
            a0 += __shfl_xor_sync(0xffffffffu, a0, o);
            a1 += __shfl_xor_sync(0xffffffffu, a1, o);
        }
        if (lane == 0) g_X[p] = make_float2(a0 + bi0, a1 + bi1);
    }
}

// ---------------------------------------------------------------------------
// Pass 2: recurrent loop. One CTA per batch element (128 CTAs, 512 threads).
// h,c state resident in registers (3 floats/thread). Per step:
//   4 block-reductions (h.Wr0, h.Wr1, c.Wc0, c.Wc1) -> 4 gate scalars ->
//   elementwise tanh(fma) update + coalesced store of ht.
// ---------------------------------------------------------------------------
__global__ void __launch_bounds__(512) recurrent_kernel(
    const float* __restrict__ h0,
    const float* __restrict__ c0,
    const float* __restrict__ Wr,
    const float* __restrict__ br,
    const float* __restrict__ Wc,
    const float* __restrict__ bc,
    float* __restrict__ out)
{
    __shared__ float2 sX[T_STEPS];       // this batch's (Xc, Xh) per timestep
    __shared__ float  sPart[4][16];      // per-warp partials, [sum_id][warp]
    __shared__ float4 sScal;             // (gha, ghb, gca, gcb)

    const int tid  = threadIdx.x;
    const int b    = blockIdx.x;
    const int warp = tid >> 5;
    const int lane = tid & 31;

    float h[3], c[3], wr0[3], wr1[3], wc0[3], wc1[3];
    #pragma unroll
    for (int j = 0; j < 3; j++) {
        const int k = j * 512 + tid;
        h[j]   = h0[b * KDIM + k];
        c[j]   = c0[b * KDIM + k];
        wr0[j] = Wr[k];
        wr1[j] = Wr[KDIM + k];
        wc0[j] = Wc[k];
        wc1[j] = Wc[KDIM + k];
    }
    if (tid < T_STEPS) sX[tid] = g_X[tid * BATCH + b];

    const float br0 = br[0], br1 = br[1];
    const float bc0 = bc[0], bc1 = bc[1];
    __syncthreads();

    for (int t = 0; t < T_STEPS; t++) {
        // per-thread partials of the 4 reductions
        float pr0 = fmaf(h[2], wr0[2], fmaf(h[1], wr0[1], h[0] * wr0[0]));  // Hc raw
        float pr1 = fmaf(h[2], wr1[2], fmaf(h[1], wr1[1], h[0] * wr1[0]));  // Hh raw
        float pc0 = fmaf(c[2], wc0[2], fmaf(c[1], wc0[1], c[0] * wc0[0]));  // Cc raw
        float pc1 = fmaf(c[2], wc1[2], fmaf(c[1], wc1[1], c[0] * wc1[0]));  // Ch raw

        #pragma unroll
        for (int o = 16; o; o >>= 1) {
            pr0 += __shfl_xor_sync(0xffffffffu, pr0, o);
            pr1 += __shfl_xor_sync(0xffffffffu, pr1, o);
            pc0 += __shfl_xor_sync(0xffffffffu, pc0, o);
            pc1 += __shfl_xor_sync(0xffffffffu, pc1, o);
        }
        if (lane == 0) {
            sPart[0][warp] = pr0;
            sPart[1][warp] = pr1;
            sPart[2][warp] = pc0;
            sPart[3][warp] = pc1;
        }
        __syncthreads();

        if (tid < 4) {
            const float4* pp = reinterpret_cast<const float4*>(sPart[tid]);
            float4 q0 = pp[0], q1 = pp[1], q2 = pp[2], q3 = pp[3];
            float s = ((q0.x + q0.y) + (q0.z + q0.w))
                    + ((q1.x + q1.y) + (q1.z + q1.w))
                    + ((q2.x + q2.y) + (q2.z + q2.w))
                    + ((q3.x + q3.y) + (q3.z + q3.w));
            // biased sums: S0=Hc=pr0+br0, S1=Hh=pr1+br1, S2=Cc=pc0+bc0, S3=Ch=pc1+bc1
            const float bias = (tid == 0) ? br0 : (tid == 1) ? br1 : (tid == 2) ? bc0 : bc1;
            s += bias;
            // scalar needs: gha<-S3(Ch), ghb<-S1(Hh), gca<-S0(Hc), gcb<-S2(Cc)
            const int src = (tid == 0) ? 3 : (tid == 1) ? 1 : (tid == 2) ? 0 : 2;
            const float ss = __shfl_sync(0xFu, s, src);
            const float sg = 1.0f / (1.0f + expf(ss));   // = 1 - sigmoid(ss)
            const float2 X = sX[t];
            const float fac = (tid == 0) ? X.y : (tid == 2) ? X.x : 1.0f;
            reinterpret_cast<float*>(&sScal)[tid] = sg * fac;
        }
        __syncthreads();

        const float4 sc = sScal;  // (gha, ghb, gca, gcb) broadcast
        float* ob = out + (long)(t * BATCH + b) * KDIM;
        #pragma unroll
        for (int j = 0; j < 3; j++) {
            h[j] = tanhf(fmaf(sc.y, h[j], sc.x));
            c[j] = tanhf(fmaf(sc.w, c[j], sc.z));
            ob[j * 512 + tid] = h[j];
        }
    }

    // final hT, cT
    const long offH = (long)T_STEPS * BATCH * KDIM;
    const long offC = offH + (long)BATCH * KDIM;
    #pragma unroll
    for (int j = 0; j < 3; j++) {
        const int k = j * 512 + tid;
        out[offH + b * KDIM + k] = h[j];
        out[offC + b * KDIM + k] = c[j];
    }
}

extern "C" void kernel_launch(void* const* d_in, const int* in_sizes, int n_in,
                              void* d_out, int out_size)
{
    const float* inputs = (const float*)d_in[0];
    const float* h0     = (const float*)d_in[1];
    const float* c0     = (const float*)d_in[2];
    const float* Wr     = (const float*)d_in[3];
    const float* br     = (const float*)d_in[4];
    const float* Wc     = (const float*)d_in[5];
    const float* bc     = (const float*)d_in[6];
    const float* Wi     = (const float*)d_in[7];
    const float* bi     = (const float*)d_in[8];
    float* out = (float*)d_out;

    precompute_x_kernel<<<(T_STEPS * BATCH) / 32, 256>>>(inputs, Wi, bi);
    recurrent_kernel<<<BATCH, 512>>>(h0, c0, Wr, br, Wc, bc, out);
}

// round 2
// speedup vs baseline: 1.2778x; 1.2778x over previous
#include <cuda_runtime.h>

#define T_STEPS 256
#define BATCH   128
#define KDIM    1536
#define K4      384     // KDIM/4

// Scratch for precomputed input projections: X[t*BATCH + b] = (Xc, Xh)
__device__ float2 g_X[T_STEPS * BATCH];

__device__ __forceinline__ void ffma2(unsigned long long& acc,
                                      unsigned long long a,
                                      unsigned long long b) {
    asm("fma.rn.f32x2 %0, %1, %2, %0;" : "+l"(acc) : "l"(a), "l"(b));
}

__device__ __forceinline__ float2 unpack2(unsigned long long v) {
    float2 f;
    asm("mov.b64 {%0, %1}, %2;" : "=f"(f.x), "=f"(f.y) : "l"(v));
    return f;
}

// fast tanh: 1 - 2/(e^{2x}+1).  2 MUFU, ~1e-7 rel err, saturates correctly.
__device__ __forceinline__ float ftanh(float x) {
    float e = __expf(2.0f * x);
    return 1.0f - __fdividef(2.0f, e + 1.0f);
}

// ---------------------------------------------------------------------------
// Pass 1: X[t,b,o] = sum_k inputs[t,b,k] * Wi[o,k] + bi[o]
// One warp per (t,b) pair, 4 pairs per warp. FFMA2 packed math (2 FMA/instr).
// ---------------------------------------------------------------------------
__global__ void __launch_bounds__(256) precompute_x_kernel(
    const float* __restrict__ in,
    const float* __restrict__ Wi,
    const float* __restrict__ bi)
{
    __shared__ ulonglong2 sW0[K4];
    __shared__ ulonglong2 sW1[K4];
    const int tid = threadIdx.x;
    const ulonglong2* Wi2 = reinterpret_cast<const ulonglong2*>(Wi);
    for (int i = tid; i < K4; i += 256) {
        sW0[i] = Wi2[i];
        sW1[i] = Wi2[K4 + i];
    }
    __syncthreads();

    const int warp = tid >> 5;
    const int lane = tid & 31;
    const float bi0 = __ldg(bi);
    const float bi1 = __ldg(bi + 1);
    const ulonglong2* in2 = reinterpret_cast<const ulonglong2*>(in);

    #pragma unroll
    for (int r = 0; r < 4; r++) {
        const int p = blockIdx.x * 32 + r * 8 + warp;   // p = t*BATCH + b
        const long base = (long)p * K4;

        unsigned long long acc00 = 0ull, acc01 = 0ull;  // out0, two chains
        unsigned long long acc10 = 0ull, acc11 = 0ull;  // out1, two chains
        #pragma unroll
        for (int i = 0; i < 12; i++) {
            ulonglong2 v  = in2[base + i * 32 + lane];
            ulonglong2 w0 = sW0[i * 32 + lane];
            ulonglong2 w1 = sW1[i * 32 + lane];
            ffma2(acc00, v.x, w0.x);
            ffma2(acc01, v.y, w0.y);
            ffma2(acc10, v.x, w1.x);
            ffma2(acc11, v.y, w1.y);
        }
        float2 p00 = unpack2(acc00), p01 = unpack2(acc01);
        float2 p10 = unpack2(acc10), p11 = unpack2(acc11);
        float a0 = (p00.x + p00.y) + (p01.x + p01.y);
        float a1 = (p10.x + p10.y) + (p11.x + p11.y);

        #pragma unroll
        for (int o = 16; o; o >>= 1) {
            a0 += __shfl_xor_sync(0xffffffffu, a0, o);
            a1 += __shfl_xor_sync(0xffffffffu, a1, o);
        }
        if (lane == 0) g_X[p] = make_float2(a0 + bi0, a1 + bi1);
    }
}

// ---------------------------------------------------------------------------
// Pass 2: recurrent loop. One CTA per batch (128 CTAs, 512 threads).
// Per step: multi-value 6-SHFL butterfly reduces 4 sums; ONE barrier
// (double-buffered partials); each warp finalizes + broadcasts scalars itself.
// ---------------------------------------------------------------------------
__global__ void __launch_bounds__(512) recurrent_kernel(
    const float* __restrict__ h0,
    const float* __restrict__ c0,
    const float* __restrict__ Wr,
    const float* __restrict__ br,
    const float* __restrict__ Wc,
    const float* __restrict__ bc,
    float* __restrict__ out)
{
    __shared__ float2 sX[T_STEPS];          // (Xc, Xh) for this batch
    __shared__ float4 sPart[2][4][4];       // [buf][sum][4x float4] = 16 partials/sum

    const int tid  = threadIdx.x;
    const int b    = blockIdx.x;
    const int warp = tid >> 5;
    const int lane = tid & 31;
    const int sid  = lane & 3;

    float h[3], c[3], wr0[3], wr1[3], wc0[3], wc1[3];
    #pragma unroll
    for (int j = 0; j < 3; j++) {
        const int k = j * 512 + tid;
        h[j]   = h0[b * KDIM + k];
        c[j]   = c0[b * KDIM + k];
        wr0[j] = Wr[k];
        wr1[j] = Wr[KDIM + k];
        wc0[j] = Wc[k];
        wc1[j] = Wc[KDIM + k];
    }
    if (tid < T_STEPS) sX[tid] = g_X[tid * BATCH + b];

    // per-lane bias for the sum this lane finalizes (sid: 0=Hc,1=Hh,2=Cc,3=Ch)
    const float mybias = (sid == 0) ? br[0] : (sid == 1) ? br[1]
                       : (sid == 2) ? bc[0] : bc[1];
    __syncthreads();

    for (int t = 0; t < T_STEPS; t++) {
        // per-thread partials: v0=Hc(h.Wr0), v1=Hh(h.Wr1), v2=Cc(c.Wc0), v3=Ch(c.Wc1)
        float v0 = fmaf(h[2], wr0[2], fmaf(h[1], wr0[1], h[0] * wr0[0]));
        float v1 = fmaf(h[2], wr1[2], fmaf(h[1], wr1[1], h[0] * wr1[0]));
        float v2 = fmaf(c[2], wc0[2], fmaf(c[1], wc0[1], c[0] * wc0[0]));
        float v3 = fmaf(c[2], wc1[2], fmaf(c[1], wc1[1], c[0] * wc1[0]));

        // multi-value butterfly: 6 SHFL, 5 levels, all 4 sums.
        // round 1 (xor16): lo half keeps sums{0,1}, hi half keeps sums{2,3}
        const bool hi = lane >= 16;
        float a  = hi ? v2 : v0;
        float bq = hi ? v3 : v1;
        float cs = hi ? v0 : v2;
        float dq = hi ? v1 : v3;
        a  += __shfl_xor_sync(0xffffffffu, cs, 16);
        bq += __shfl_xor_sync(0xffffffffu, dq, 16);
        // round 2 (xor8): specialize to one sum per lane
        const bool sel = (lane & 8) != 0;
        float keep = sel ? bq : a;
        float send = sel ? a : bq;
        float x = keep + __shfl_xor_sync(0xffffffffu, send, 8);
        // rounds 3-5
        x += __shfl_xor_sync(0xffffffffu, x, 4);
        x += __shfl_xor_sync(0xffffffffu, x, 2);
        x += __shfl_xor_sync(0xffffffffu, x, 1);
        // lane L now holds the full warp sum of sum_id = (L>>3)&3

        const int buf = t & 1;
        if ((lane & 7) == 0)
            reinterpret_cast<float*>(sPart[buf][lane >> 3])[warp] = x;
        __syncthreads();

        // each lane reduces row `sid` (16 cross-warp partials); lanes 0-3 matter
        const float4* rp = sPart[buf][sid];
        float4 q0 = rp[0], q1 = rp[1], q2 = rp[2], q3 = rp[3];
        float s = ((q0.x + q0.y) + (q0.z + q0.w))
                + ((q1.x + q1.y) + (q1.z + q1.w))
                + ((q2.x + q2.y) + (q2.z + q2.w))
                + ((q3.x + q3.y) + (q3.z + q3.w));
        s += mybias;

        const float e  = __expf(s);
        const float sg = __fdividef(1.0f, 1.0f + e);   // 1 - sigmoid(s)
        const float2 X = sX[t];
        const float fac = (sid == 3) ? X.y : (sid == 0) ? X.x : 1.0f;
        const float g = sg * fac;

        // broadcast: gca from lane0(Hc*Xc), ghb lane1(Hh), gcb lane2(Cc), gha lane3(Ch*Xh)
        const float gca = __shfl_sync(0xffffffffu, g, 0);
        const float ghb = __shfl_sync(0xffffffffu, g, 1);
        const float gcb = __shfl_sync(0xffffffffu, g, 2);
        const float gha = __shfl_sync(0xffffffffu, g, 3);

        float* ob = out + (long)(t * BATCH + b) * KDIM;
        #pragma unroll
        for (int j = 0; j < 3; j++) {
            h[j] = ftanh(fmaf(ghb, h[j], gha));
            c[j] = ftanh(fmaf(gcb, c[j], gca));
            ob[j * 512 + tid] = h[j];
        }
    }

    const long offH = (long)T_STEPS * BATCH * KDIM;
    const long offC = offH + (long)BATCH * KDIM;
    #pragma unroll
    for (int j = 0; j < 3; j++) {
        const int k = j * 512 + tid;
        out[offH + b * KDIM + k] = h[j];
        out[offC + b * KDIM + k] = c[j];
    }
}

extern "C" void kernel_launch(void* const* d_in, const int* in_sizes, int n_in,
                              void* d_out, int out_size)
{
    const float* inputs = (const float*)d_in[0];
    const float* h0     = (const float*)d_in[1];
    const float* c0     = (const float*)d_in[2];
    const float* Wr     = (const float*)d_in[3];
    const float* br     = (const float*)d_in[4];
    const float* Wc     = (const float*)d_in[5];
    const float* bc     = (const float*)d_in[6];
    const float* Wi     = (const float*)d_in[7];
    const float* bi     = (const float*)d_in[8];
    float* out = (float*)d_out;

    precompute_x_kernel<<<(T_STEPS * BATCH) / 32, 256>>>(inputs, Wi, bi);
    recurrent_kernel<<<BATCH, 512>>>(h0, c0, Wr, br, Wc, bc, out);
}

// round 3
// speedup vs baseline: 1.4436x; 1.1297x over previous
#include <cuda_runtime.h>

#define T_STEPS 256
#define BATCH   128
#define KDIM    1536
#define K4      384     // KDIM/4

// Scratch for precomputed input projections: X[t*BATCH + b] = (Xc, Xh)
__device__ float2 g_X[T_STEPS * BATCH];

__device__ __forceinline__ void ffma2(unsigned long long& acc,
                                      unsigned long long a,
                                      unsigned long long b) {
    asm("fma.rn.f32x2 %0, %1, %2, %0;" : "+l"(acc) : "l"(a), "l"(b));
}

__device__ __forceinline__ float2 unpack2(unsigned long long v) {
    float2 f;
    asm("mov.b64 {%0, %1}, %2;" : "=f"(f.x), "=f"(f.y) : "l"(v));
    return f;
}

// HW tanh: single MUFU op (sm_75+), max rel err ~2^-11.
__device__ __forceinline__ float tanha(float x) {
    float y;
    asm("tanh.approx.f32 %0, %1;" : "=f"(y) : "f"(x));
    return y;
}

// ---------------------------------------------------------------------------
// Pass 1: X[t,b,o] = sum_k inputs[t,b,k] * Wi[o,k] + bi[o]
// One warp handles 4 (t,b) pairs, processed 2-at-a-time for 24 LDG.128 MLP.
// ---------------------------------------------------------------------------
__global__ void __launch_bounds__(256) precompute_x_kernel(
    const float* __restrict__ in,
    const float* __restrict__ Wi,
    const float* __restrict__ bi)
{
    __shared__ ulonglong2 sW0[K4];
    __shared__ ulonglong2 sW1[K4];
    const int tid = threadIdx.x;
    const ulonglong2* Wi2 = reinterpret_cast<const ulonglong2*>(Wi);
    for (int i = tid; i < K4; i += 256) {
        sW0[i] = Wi2[i];
        sW1[i] = Wi2[K4 + i];
    }
    __syncthreads();

    const int warp = tid >> 5;
    const int lane = tid & 31;
    const float bi0 = __ldg(bi);
    const float bi1 = __ldg(bi + 1);
    const ulonglong2* in2 = reinterpret_cast<const ulonglong2*>(in);

    #pragma unroll
    for (int r = 0; r < 2; r++) {
        const int pA = blockIdx.x * 32 + r * 16 + warp;   // p = t*BATCH + b
        const int pB = pA + 8;
        const long baseA = (long)pA * K4;
        const long baseB = (long)pB * K4;

        unsigned long long aA00 = 0ull, aA01 = 0ull, aA10 = 0ull, aA11 = 0ull;
        unsigned long long aB00 = 0ull, aB01 = 0ull, aB10 = 0ull, aB11 = 0ull;
        #pragma unroll
        for (int i = 0; i < 12; i++) {
            ulonglong2 vA = in2[baseA + i * 32 + lane];
            ulonglong2 vB = in2[baseB + i * 32 + lane];
            ulonglong2 w0 = sW0[i * 32 + lane];
            ulonglong2 w1 = sW1[i * 32 + lane];
            ffma2(aA00, vA.x, w0.x);
            ffma2(aA01, vA.y, w0.y);
            ffma2(aA10, vA.x, w1.x);
            ffma2(aA11, vA.y, w1.y);
            ffma2(aB00, vB.x, w0.x);
            ffma2(aB01, vB.y, w0.y);
            ffma2(aB10, vB.x, w1.x);
            ffma2(aB11, vB.y, w1.y);
        }
        float2 qA00 = unpack2(aA00), qA01 = unpack2(aA01);
        float2 qA10 = unpack2(aA10), qA11 = unpack2(aA11);
        float2 qB00 = unpack2(aB00), qB01 = unpack2(aB01);
        float2 qB10 = unpack2(aB10), qB11 = unpack2(aB11);
        float a0 = (qA00.x + qA00.y) + (qA01.x + qA01.y);
        float a1 = (qA10.x + qA10.y) + (qA11.x + qA11.y);
        float b0 = (qB00.x + qB00.y) + (qB01.x + qB01.y);
        float b1 = (qB10.x + qB10.y) + (qB11.x + qB11.y);

        #pragma unroll
        for (int o = 16; o; o >>= 1) {
            a0 += __shfl_xor_sync(0xffffffffu, a0, o);
            a1 += __shfl_xor_sync(0xffffffffu, a1, o);
            b0 += __shfl_xor_sync(0xffffffffu, b0, o);
            b1 += __shfl_xor_sync(0xffffffffu, b1, o);
        }
        if (lane == 0) {
            g_X[pA] = make_float2(a0 + bi0, a1 + bi1);
            g_X[pB] = make_float2(b0 + bi0, b1 + bi1);
        }
    }
}

// ---------------------------------------------------------------------------
// Pass 2: recurrent loop. One CTA per batch (128 CTAs, 512 threads).
// Per step: multi-value 6-SHFL butterfly reduces 4 sums; ONE barrier
// (double-buffered partials); HW tanh.approx for gates + state (1 MUFU each).
// ---------------------------------------------------------------------------
__global__ void __launch_bounds__(512) recurrent_kernel(
    const float* __restrict__ h0,
    const float* __restrict__ c0,
    const float* __restrict__ Wr,
    const float* __restrict__ br,
    const float* __restrict__ Wc,
    const float* __restrict__ bc,
    float* __restrict__ out)
{
    __shared__ float2 sX[T_STEPS];          // (Xc, Xh) for this batch
    __shared__ float4 sPart[2][4][4];       // [buf][sum][4x float4] = 16 partials/sum

    const int tid  = threadIdx.x;
    const int b    = blockIdx.x;
    const int warp = tid >> 5;
    const int lane = tid & 31;
    const int sid  = lane & 3;

    float h[3], c[3], wr0[3], wr1[3], wc0[3], wc1[3];
    #pragma unroll
    for (int j = 0; j < 3; j++) {
        const int k = j * 512 + tid;
        h[j]   = h0[b * KDIM + k];
        c[j]   = c0[b * KDIM + k];
        wr0[j] = Wr[k];
        wr1[j] = Wr[KDIM + k];
        wc0[j] = Wc[k];
        wc1[j] = Wc[KDIM + k];
    }
    if (tid < T_STEPS) sX[tid] = g_X[tid * BATCH + b];

    // per-lane bias for the sum this lane finalizes (sid: 0=Hc,1=Hh,2=Cc,3=Ch)
    const float mybias = (sid == 0) ? br[0] : (sid == 1) ? br[1]
                       : (sid == 2) ? bc[0] : bc[1];
    __syncthreads();

    for (int t = 0; t < T_STEPS; t++) {
        // per-thread partials: v0=Hc(h.Wr0), v1=Hh(h.Wr1), v2=Cc(c.Wc0), v3=Ch(c.Wc1)
        float v0 = fmaf(h[2], wr0[2], fmaf(h[1], wr0[1], h[0] * wr0[0]));
        float v1 = fmaf(h[2], wr1[2], fmaf(h[1], wr1[1], h[0] * wr1[0]));
        float v2 = fmaf(c[2], wc0[2], fmaf(c[1], wc0[1], c[0] * wc0[0]));
        float v3 = fmaf(c[2], wc1[2], fmaf(c[1], wc1[1], c[0] * wc1[0]));

        // multi-value butterfly: 6 SHFL, 5 levels, all 4 sums.
        const bool hi = lane >= 16;
        float a  = hi ? v2 : v0;
        float bq = hi ? v3 : v1;
        float cs = hi ? v0 : v2;
        float dq = hi ? v1 : v3;
        a  += __shfl_xor_sync(0xffffffffu, cs, 16);
        bq += __shfl_xor_sync(0xffffffffu, dq, 16);
        const bool sel = (lane & 8) != 0;
        float keep = sel ? bq : a;
        float send = sel ? a : bq;
        float x = keep + __shfl_xor_sync(0xffffffffu, send, 8);
        x += __shfl_xor_sync(0xffffffffu, x, 4);
        x += __shfl_xor_sync(0xffffffffu, x, 2);
        x += __shfl_xor_sync(0xffffffffu, x, 1);
        // lane L now holds the full warp sum of sum_id = (L>>3)&3

        const int buf = t & 1;
        if ((lane & 7) == 0)
            reinterpret_cast<float*>(sPart[buf][lane >> 3])[warp] = x;
        __syncthreads();

        // each lane reduces row `sid` (16 cross-warp partials)
        const float4* rp = sPart[buf][sid];
        float4 q0 = rp[0], q1 = rp[1], q2 = rp[2], q3 = rp[3];
        float s = ((q0.x + q0.y) + (q0.z + q0.w))
                + ((q1.x + q1.y) + (q1.z + q1.w))
                + ((q2.x + q2.y) + (q2.z + q2.w))
                + ((q3.x + q3.y) + (q3.z + q3.w));
        s += mybias;

        // 1 - sigmoid(s) = 0.5 - 0.5*tanh(s/2)  (single MUFU)
        const float sg = fmaf(-0.5f, tanha(0.5f * s), 0.5f);
        const float2 X = sX[t];
        const float fac = (sid == 3) ? X.y : (sid == 0) ? X.x : 1.0f;
        const float g = sg * fac;

        // broadcast: gca lane0(Hc*Xc), ghb lane1(Hh), gcb lane2(Cc), gha lane3(Ch*Xh)
        const float gca = __shfl_sync(0xffffffffu, g, 0);
        const float ghb = __shfl_sync(0xffffffffu, g, 1);
        const float gcb = __shfl_sync(0xffffffffu, g, 2);
        const float gha = __shfl_sync(0xffffffffu, g, 3);

        float* ob = out + (long)(t * BATCH + b) * KDIM;
        #pragma unroll
        for (int j = 0; j < 3; j++) {
            h[j] = tanha(fmaf(ghb, h[j], gha));
            c[j] = tanha(fmaf(gcb, c[j], gca));
            ob[j * 512 + tid] = h[j];
        }
    }

    const long offH = (long)T_STEPS * BATCH * KDIM;
    const long offC = offH + (long)BATCH * KDIM;
    #pragma unroll
    for (int j = 0; j < 3; j++) {
        const int k = j * 512 + tid;
        out[offH + b * KDIM + k] = h[j];
        out[offC + b * KDIM + k] = c[j];
    }
}

extern "C" void kernel_launch(void* const* d_in, const int* in_sizes, int n_in,
                              void* d_out, int out_size)
{
    const float* inputs = (const float*)d_in[0];
    const float* h0     = (const float*)d_in[1];
    const float* c0     = (const float*)d_in[2];
    const float* Wr     = (const float*)d_in[3];
    const float* br     = (const float*)d_in[4];
    const float* Wc     = (const float*)d_in[5];
    const float* bc     = (const float*)d_in[6];
    const float* Wi     = (const float*)d_in[7];
    const float* bi     = (const float*)d_in[8];
    float* out = (float*)d_out;

    precompute_x_kernel<<<(T_STEPS * BATCH) / 32, 256>>>(inputs, Wi, bi);
    recurrent_kernel<<<BATCH, 512>>>(h0, c0, Wr, br, Wc, bc, out);
}

// round 4
// speedup vs baseline: 1.6741x; 1.1597x over previous
#include <cuda_runtime.h>

#define T_STEPS 256
#define BATCH   128
#define KDIM    1536
#define F2      768    // KDIM/2 (float2 units)

// HW tanh: single MUFU op, max rel err ~2^-11.
__device__ __forceinline__ float tanha(float x) {
    float y;
    asm("tanh.approx.f32 %0, %1;" : "=f"(y) : "f"(x));
    return y;
}

// ---------------------------------------------------------------------------
// Fully fused kernel: one CTA per batch element, 256 threads (8 warps).
// Thread owns 3 float2 slots of the 1536-dim state (float2-index tid+256j).
// Per step: 6-sum butterfly (4 gates for step t + 2 input-projection sums for
// step t+1), one barrier, tail finalize + 6 SHFL broadcasts, state update.
// Input x is prefetched one step ahead of its projection (two ahead of use).
// ---------------------------------------------------------------------------
__global__ void __launch_bounds__(256) fused_kernel(
    const float* __restrict__ inputs,
    const float* __restrict__ h0,
    const float* __restrict__ c0,
    const float* __restrict__ Wr,
    const float* __restrict__ br,
    const float* __restrict__ Wc,
    const float* __restrict__ bc,
    const float* __restrict__ Wi,
    const float* __restrict__ bi,
    float* __restrict__ out)
{
    __shared__ float4 sPart[2][8][2];   // [buf][row][8 floats]: rows 0-5 used

    const int tid  = threadIdx.x;
    const int b    = blockIdx.x;
    const int warp = tid >> 5;
    const int lane = tid & 31;

    const float2* in2 = (const float2*)inputs;
    const float2* h02 = (const float2*)h0;
    const float2* c02 = (const float2*)c0;
    const float2* Wr2 = (const float2*)Wr;
    const float2* Wc2 = (const float2*)Wc;
    const float2* Wi2 = (const float2*)Wi;
    float2* out2 = (float2*)out;

    float2 h[3], c[3], wr0[3], wr1[3], wc0[3], wc1[3], wi0[3], wi1[3];
    #pragma unroll
    for (int j = 0; j < 3; j++) {
        const int p = tid + 256 * j;
        h[j]   = h02[b * F2 + p];
        c[j]   = c02[b * F2 + p];
        wr0[j] = Wr2[p];        wr1[j] = Wr2[F2 + p];
        wc0[j] = Wc2[p];        wc1[j] = Wc2[F2 + p];
        wi0[j] = Wi2[p];        wi1[j] = Wi2[F2 + p];
    }
    const float br0 = br[0], br1 = br[1];
    const float bc0 = bc[0], bc1 = bc[1];
    const float bi0 = bi[0], bi1 = bi[1];

    // lane roles
    const int  rid = lane & 7;      // tail row this lane reduces (0-5 real)
    const bool lo  = lane < 16;
    const bool b3  = (lane & 8) != 0;
    const bool b2  = (lane & 4) != 0;
    const bool writer = lo ? ((lane & 3) == 0) : ((lane & 7) == 0);
    const int  wrow   = lo ? (((lane >> 3) & 1) * 2 + ((lane >> 2) & 1))
                           : (4 + ((lane >> 3) & 1));
    const float mybias = (rid == 0) ? br0 : (rid == 1) ? br1
                       : (rid == 2) ? bc0 : (rid == 3) ? bc1
                       : (rid == 4) ? bi0 : (rid == 5) ? bi1 : 0.0f;

    // ---- prologue: full reduction of X0 = Wi.x_0 + bi; preload xa = x_1 ----
    float2 xa[3], xb[3];
    {
        float v4 = 0.0f, v5 = 0.0f;
        #pragma unroll
        for (int j = 0; j < 3; j++) {
            const int p = tid + 256 * j;
            float2 x0 = in2[(long)b * F2 + p];                       // t = 0
            v4 = fmaf(x0.x, wi0[j].x, fmaf(x0.y, wi0[j].y, v4));
            v5 = fmaf(x0.x, wi1[j].x, fmaf(x0.y, wi1[j].y, v5));
            xa[j] = in2[(long)BATCH * F2 + (long)b * F2 + p];        // t = 1
        }
        float k = lo ? v4 : v5;
        float s = lo ? v5 : v4;
        k += __shfl_xor_sync(~0u, s, 16);
        k += __shfl_xor_sync(~0u, k, 8);
        k += __shfl_xor_sync(~0u, k, 4);
        k += __shfl_xor_sync(~0u, k, 2);
        k += __shfl_xor_sync(~0u, k, 1);
        if (lane == 0)  ((float*)&sPart[1][4][0])[warp] = k;
        if (lane == 16) ((float*)&sPart[1][5][0])[warp] = k;
    }
    __syncthreads();
    float Xc, Xh;
    {
        float4 a0 = sPart[1][4][0], a1 = sPart[1][4][1];
        float4 d0 = sPart[1][5][0], d1 = sPart[1][5][1];
        Xc = ((a0.x + a0.y) + (a0.z + a0.w)) + ((a1.x + a1.y) + (a1.z + a1.w)) + bi0;
        Xh = ((d0.x + d0.y) + (d0.z + d0.w)) + ((d1.x + d1.y) + (d1.z + d1.w)) + bi1;
    }

    for (int t = 0; t < T_STEPS; t++) {
        // prefetch x_{t+2} (consumed by the butterfly of step t+1)
        const int tp = (t + 2 < T_STEPS) ? t + 2 : T_STEPS - 1;
        const long xbase = (long)tp * BATCH * F2 + (long)b * F2;
        #pragma unroll
        for (int j = 0; j < 3; j++) xb[j] = in2[xbase + tid + 256 * j];

        // per-thread partials: g0=Hc g1=Hh g2=Cc g3=Ch, x4=Xc(t+1) x5=Xh(t+1)
        float g0 = 0, g1 = 0, g2 = 0, g3 = 0, x4 = 0, x5 = 0;
        #pragma unroll
        for (int j = 0; j < 3; j++) {
            g0 = fmaf(h[j].x, wr0[j].x, fmaf(h[j].y, wr0[j].y, g0));
            g1 = fmaf(h[j].x, wr1[j].x, fmaf(h[j].y, wr1[j].y, g1));
            g2 = fmaf(c[j].x, wc0[j].x, fmaf(c[j].y, wc0[j].y, g2));
            g3 = fmaf(c[j].x, wc1[j].x, fmaf(c[j].y, wc1[j].y, g3));
            x4 = fmaf(xa[j].x, wi0[j].x, fmaf(xa[j].y, wi0[j].y, x4));
            x5 = fmaf(xa[j].x, wi1[j].x, fmaf(xa[j].y, wi1[j].y, x5));
        }

        // ---- 6-sum butterfly: 9 SHFL, 5 levels ----
        // L1 (xor16): lo half accumulates g0-g3, hi half accumulates x4,x5
        float rA = __shfl_xor_sync(~0u, lo ? x4 : g0, 16);
        float rB = __shfl_xor_sync(~0u, lo ? x5 : g1, 16);
        float rC = __shfl_xor_sync(~0u, g2, 16);
        float rD = __shfl_xor_sync(~0u, g3, 16);
        if (lo) { g0 += rA; g1 += rB; g2 += rC; g3 += rD; }
        else    { x4 += rA; x5 += rB; }
        // L2 (xor8): lo keeps 2 sums (b3 ? {g2,g3} : {g0,g1}); hi keeps 1 X
        float P  = lo ? (b3 ? g2 : g0) : (b3 ? x5 : x4);
        float sP = lo ? (b3 ? g0 : g2) : (b3 ? x4 : x5);
        P += __shfl_xor_sync(~0u, sP, 8);
        float Q  = b3 ? g3 : g1;            // meaningful for lo only
        float sQ = b3 ? g1 : g3;
        Q += __shfl_xor_sync(~0u, sQ, 8);
        // L3 (xor4): lo specializes P/Q by b2; hi pure reduce
        float R  = lo ? (b2 ? Q : P) : P;
        float sR = lo ? (b2 ? P : Q) : P;
        R += __shfl_xor_sync(~0u, sR, 4);
        // L4, L5: pure reduce
        R += __shfl_xor_sync(~0u, R, 2);
        R += __shfl_xor_sync(~0u, R, 1);
        // lane holds full warp sum of id: lo -> b3*2+b2 (gates), hi -> 4+b3 (X)

        const int buf = t & 1;
        if (writer) ((float*)&sPart[buf][wrow][0])[warp] = R;
        __syncthreads();

        // ---- tail: reduce 8 cross-warp partials of row rid ----
        float4 q0 = sPart[buf][rid][0];
        float4 q1 = sPart[buf][rid][1];
        float s = ((q0.x + q0.y) + (q0.z + q0.w))
                + ((q1.x + q1.y) + (q1.z + q1.w)) + mybias;

        float gval;
        if (rid < 4) {
            // 1 - sigmoid(s) = 0.5 - 0.5*tanh(s/2)
            float sg  = fmaf(-0.5f, tanha(0.5f * s), 0.5f);
            float fac = (rid == 0) ? Xc : (rid == 3) ? Xh : 1.0f;
            gval = sg * fac;
        } else {
            gval = s;   // X sums for step t+1
        }
        const float gca = __shfl_sync(~0u, gval, 0);   // (1-sig(Hc))*Xc
        const float ghb = __shfl_sync(~0u, gval, 1);   // (1-sig(Hh))
        const float gcb = __shfl_sync(~0u, gval, 2);   // (1-sig(Cc))
        const float gha = __shfl_sync(~0u, gval, 3);   // (1-sig(Ch))*Xh
        Xc = __shfl_sync(~0u, gval, 4);
        Xh = __shfl_sync(~0u, gval, 5);

        float2* ob = out2 + ((long)t * BATCH + b) * F2;
        #pragma unroll
        for (int j = 0; j < 3; j++) {
            h[j].x = tanha(fmaf(ghb, h[j].x, gha));
            h[j].y = tanha(fmaf(ghb, h[j].y, gha));
            c[j].x = tanha(fmaf(gcb, c[j].x, gca));
            c[j].y = tanha(fmaf(gcb, c[j].y, gca));
            ob[tid + 256 * j] = h[j];
        }
        xa[0] = xb[0]; xa[1] = xb[1]; xa[2] = xb[2];
    }

    // final hT, cT
    const long offH = (long)T_STEPS * BATCH * F2;
    const long offC = offH + (long)BATCH * F2;
    #pragma unroll
    for (int j = 0; j < 3; j++) {
        const int p = tid + 256 * j;
        out2[offH + (long)b * F2 + p] = h[j];
        out2[offC + (long)b * F2 + p] = c[j];
    }
}

extern "C" void kernel_launch(void* const* d_in, const int* in_sizes, int n_in,
                              void* d_out, int out_size)
{
    const float* inputs = (const float*)d_in[0];
    const float* h0     = (const float*)d_in[1];
    const float* c0     = (const float*)d_in[2];
    const float* Wr     = (const float*)d_in[3];
    const float* br     = (const float*)d_in[4];
    const float* Wc     = (const float*)d_in[5];
    const float* bc     = (const float*)d_in[6];
    const float* Wi     = (const float*)d_in[7];
    const float* bi     = (const float*)d_in[8];
    float* out = (float*)d_out;

    fused_kernel<<<BATCH, 256>>>(inputs, h0, c0, Wr, br, Wc, bc, Wi, bi, out);
}

// round 5
// speedup vs baseline: 1.9865x; 1.1866x over previous
#include <cuda_runtime.h>

#define T_STEPS 256
#define BATCH   128
#define KDIM    1536
#define F2      768    // KDIM/2 (float2 units)

// HW tanh: single MUFU op, max rel err ~2^-11.
__device__ __forceinline__ float tanha(float x) {
    float y;
    asm("tanh.approx.f32 %0, %1;" : "=f"(y) : "f"(x));
    return y;
}

// ---------------------------------------------------------------------------
// Fully fused kernel: one CTA per batch element, 256 threads (8 warps).
// Thread owns 3 float2 slots of the 1536-dim state (float2-index tid+256j).
// Per step: 6-sum butterfly (4 gates for step t + 2 input-projection sums for
// step t+1), one barrier, tail finalize + 6 SHFL broadcasts, state update.
// Input x is prefetched with a 2-step pipeline (xa/xb/xc) so the DRAM
// round-trip has a ~2-step budget and is off the critical path.
// ---------------------------------------------------------------------------
__global__ void __launch_bounds__(256) fused_kernel(
    const float* __restrict__ inputs,
    const float* __restrict__ h0,
    const float* __restrict__ c0,
    const float* __restrict__ Wr,
    const float* __restrict__ br,
    const float* __restrict__ Wc,
    const float* __restrict__ bc,
    const float* __restrict__ Wi,
    const float* __restrict__ bi,
    float* __restrict__ out)
{
    __shared__ float4 sPart[2][8][2];   // [buf][row][8 floats]: rows 0-5 used

    const int tid  = threadIdx.x;
    const int b    = blockIdx.x;
    const int warp = tid >> 5;
    const int lane = tid & 31;

    const float2* in2 = (const float2*)inputs;
    const float2* h02 = (const float2*)h0;
    const float2* c02 = (const float2*)c0;
    const float2* Wr2 = (const float2*)Wr;
    const float2* Wc2 = (const float2*)Wc;
    const float2* Wi2 = (const float2*)Wi;
    float2* out2 = (float2*)out;

    float2 h[3], c[3], wr0[3], wr1[3], wc0[3], wc1[3], wi0[3], wi1[3];
    #pragma unroll
    for (int j = 0; j < 3; j++) {
        const int p = tid + 256 * j;
        h[j]   = h02[b * F2 + p];
        c[j]   = c02[b * F2 + p];
        wr0[j] = Wr2[p];        wr1[j] = Wr2[F2 + p];
        wc0[j] = Wc2[p];        wc1[j] = Wc2[F2 + p];
        wi0[j] = Wi2[p];        wi1[j] = Wi2[F2 + p];
    }
    const float br0 = br[0], br1 = br[1];
    const float bc0 = bc[0], bc1 = bc[1];
    const float bi0 = bi[0], bi1 = bi[1];

    // lane roles
    const int  rid = lane & 7;      // tail row this lane reduces (0-5 real)
    const bool lo  = lane < 16;
    const bool b3  = (lane & 8) != 0;
    const bool b2  = (lane & 4) != 0;
    const bool writer = lo ? ((lane & 3) == 0) : ((lane & 7) == 0);
    const int  wrow   = lo ? (((lane >> 3) & 1) * 2 + ((lane >> 2) & 1))
                           : (4 + ((lane >> 3) & 1));
    const float mybias = (rid == 0) ? br0 : (rid == 1) ? br1
                       : (rid == 2) ? bc0 : (rid == 3) ? bc1
                       : (rid == 4) ? bi0 : (rid == 5) ? bi1 : 0.0f;

    // ---- prologue: full reduction of X0 = Wi.x_0 + bi; preload x1, x2 ----
    float2 xa[3], xb[3], xc[3];
    {
        float v4 = 0.0f, v5 = 0.0f;
        #pragma unroll
        for (int j = 0; j < 3; j++) {
            const int p = tid + 256 * j;
            float2 x0 = in2[(long)b * F2 + p];                           // t=0
            v4 = fmaf(x0.x, wi0[j].x, fmaf(x0.y, wi0[j].y, v4));
            v5 = fmaf(x0.x, wi1[j].x, fmaf(x0.y, wi1[j].y, v5));
            xa[j] = in2[(long)1 * BATCH * F2 + (long)b * F2 + p];        // t=1
            xb[j] = in2[(long)2 * BATCH * F2 + (long)b * F2 + p];        // t=2
        }
        float k = lo ? v4 : v5;
        float s = lo ? v5 : v4;
        k += __shfl_xor_sync(~0u, s, 16);
        k += __shfl_xor_sync(~0u, k, 8);
        k += __shfl_xor_sync(~0u, k, 4);
        k += __shfl_xor_sync(~0u, k, 2);
        k += __shfl_xor_sync(~0u, k, 1);
        if (lane == 0)  ((float*)&sPart[1][4][0])[warp] = k;
        if (lane == 16) ((float*)&sPart[1][5][0])[warp] = k;
    }
    __syncthreads();
    float Xc, Xh;
    {
        float4 a0 = sPart[1][4][0], a1 = sPart[1][4][1];
        float4 d0 = sPart[1][5][0], d1 = sPart[1][5][1];
        Xc = ((a0.x + a0.y) + (a0.z + a0.w)) + ((a1.x + a1.y) + (a1.z + a1.w)) + bi0;
        Xh = ((d0.x + d0.y) + (d0.z + d0.w)) + ((d1.x + d1.y) + (d1.z + d1.w)) + bi1;
    }

    #pragma unroll 2
    for (int t = 0; t < T_STEPS; t++) {
        // prefetch x_{t+3}: 2-step latency budget (consumed at step t+2)
        const int tp = (t + 3 < T_STEPS) ? t + 3 : T_STEPS - 1;
        const long xbase = (long)tp * BATCH * F2 + (long)b * F2;
        #pragma unroll
        for (int j = 0; j < 3; j++) xc[j] = in2[xbase + tid + 256 * j];

        // per-thread partials: g0=Hc g1=Hh g2=Cc g3=Ch, x4=Xc(t+1) x5=Xh(t+1)
        float g0 = 0, g1 = 0, g2 = 0, g3 = 0, x4 = 0, x5 = 0;
        #pragma unroll
        for (int j = 0; j < 3; j++) {
            g0 = fmaf(h[j].x, wr0[j].x, fmaf(h[j].y, wr0[j].y, g0));
            g1 = fmaf(h[j].x, wr1[j].x, fmaf(h[j].y, wr1[j].y, g1));
            g2 = fmaf(c[j].x, wc0[j].x, fmaf(c[j].y, wc0[j].y, g2));
            g3 = fmaf(c[j].x, wc1[j].x, fmaf(c[j].y, wc1[j].y, g3));
            x4 = fmaf(xa[j].x, wi0[j].x, fmaf(xa[j].y, wi0[j].y, x4));
            x5 = fmaf(xa[j].x, wi1[j].x, fmaf(xa[j].y, wi1[j].y, x5));
        }

        // ---- 6-sum butterfly: 9 SHFL, 5 levels ----
        // L1 (xor16): lo half accumulates g0-g3, hi half accumulates x4,x5
        float rA = __shfl_xor_sync(~0u, lo ? x4 : g0, 16);
        float rB = __shfl_xor_sync(~0u, lo ? x5 : g1, 16);
        float rC = __shfl_xor_sync(~0u, g2, 16);
        float rD = __shfl_xor_sync(~0u, g3, 16);
        if (lo) { g0 += rA; g1 += rB; g2 += rC; g3 += rD; }
        else    { x4 += rA; x5 += rB; }
        // L2 (xor8): lo keeps 2 sums (b3 ? {g2,g3} : {g0,g1}); hi keeps 1 X
        float P  = lo ? (b3 ? g2 : g0) : (b3 ? x5 : x4);
        float sP = lo ? (b3 ? g0 : g2) : (b3 ? x4 : x5);
        P += __shfl_xor_sync(~0u, sP, 8);
        float Q  = b3 ? g3 : g1;            // meaningful for lo only
        float sQ = b3 ? g1 : g3;
        Q += __shfl_xor_sync(~0u, sQ, 8);
        // L3 (xor4): lo specializes P/Q by b2; hi pure reduce
        float R  = lo ? (b2 ? Q : P) : P;
        float sR = lo ? (b2 ? P : Q) : P;
        R += __shfl_xor_sync(~0u, sR, 4);
        // L4, L5: pure reduce
        R += __shfl_xor_sync(~0u, R, 2);
        R += __shfl_xor_sync(~0u, R, 1);
        // lane holds full warp sum of id: lo -> b3*2+b2 (gates), hi -> 4+b3 (X)

        const int buf = t & 1;
        if (writer) ((float*)&sPart[buf][wrow][0])[warp] = R;
        __syncthreads();

        // ---- tail: reduce 8 cross-warp partials of row rid ----
        float4 q0 = sPart[buf][rid][0];
        float4 q1 = sPart[buf][rid][1];
        float s = ((q0.x + q0.y) + (q0.z + q0.w))
                + ((q1.x + q1.y) + (q1.z + q1.w)) + mybias;

        float gval;
        if (rid < 4) {
            // 1 - sigmoid(s) = 0.5 - 0.5*tanh(s/2)
            float sg  = fmaf(-0.5f, tanha(0.5f * s), 0.5f);
            float fac = (rid == 0) ? Xc : (rid == 3) ? Xh : 1.0f;
            gval = sg * fac;
        } else {
            gval = s;   // X sums for step t+1
        }
        const float gca = __shfl_sync(~0u, gval, 0);   // (1-sig(Hc))*Xc
        const float ghb = __shfl_sync(~0u, gval, 1);   // (1-sig(Hh))
        const float gcb = __shfl_sync(~0u, gval, 2);   // (1-sig(Cc))
        const float gha = __shfl_sync(~0u, gval, 3);   // (1-sig(Ch))*Xh
        Xc = __shfl_sync(~0u, gval, 4);
        Xh = __shfl_sync(~0u, gval, 5);

        float2* ob = out2 + ((long)t * BATCH + b) * F2;
        #pragma unroll
        for (int j = 0; j < 3; j++) {
            h[j].x = tanha(fmaf(ghb, h[j].x, gha));
            h[j].y = tanha(fmaf(ghb, h[j].y, gha));
            c[j].x = tanha(fmaf(gcb, c[j].x, gca));
            c[j].y = tanha(fmaf(gcb, c[j].y, gca));
            ob[tid + 256 * j] = h[j];
        }
        // rotate prefetch pipeline (renamed away by unroll-2)
        #pragma unroll
        for (int j = 0; j < 3; j++) { xa[j] = xb[j]; xb[j] = xc[j]; }
    }

    // final hT, cT
    const long offH = (long)T_STEPS * BATCH * F2;
    const long offC = offH + (long)BATCH * F2;
    #pragma unroll
    for (int j = 0; j < 3; j++) {
        const int p = tid + 256 * j;
        out2[offH + (long)b * F2 + p] = h[j];
        out2[offC + (long)b * F2 + p] = c[j];
    }
}

extern "C" void kernel_launch(void* const* d_in, const int* in_sizes, int n_in,
                              void* d_out, int out_size)
{
    const float* inputs = (const float*)d_in[0];
    const float* h0     = (const float*)d_in[1];
    const float* c0     = (const float*)d_in[2];
    const float* Wr     = (const float*)d_in[3];
    const float* br     = (const float*)d_in[4];
    const float* Wc     = (const float*)d_in[5];
    const float* bc     = (const float*)d_in[6];
    const float* Wi     = (const float*)d_in[7];
    const float* bi     = (const float*)d_in[8];
    float* out = (float*)d_out;

    fused_kernel<<<BATCH, 256>>>(inputs, h0, c0, Wr, br, Wc, bc, Wi, bi, out);
}

// round 7
// speedup vs baseline: 2.1240x; 1.0692x over previous
#include <cuda_runtime.h>

#define T_STEPS 256
#define BATCH   128
#define KDIM    1536
#define F2      768    // KDIM/2 (float2 units)

// HW tanh: single MUFU op, max rel err ~2^-11.
__device__ __forceinline__ float tanha(float x) {
    float y;
    asm("tanh.approx.f32 %0, %1;" : "=f"(y) : "f"(x));
    return y;
}

// ---------------------------------------------------------------------------
// One recurrent step. X holds x_{t+1} on entry (consumed for the t+1 input
// projection), and is overwritten with x_{t+5} (4-step prefetch budget).
// ---------------------------------------------------------------------------
__device__ __forceinline__ void do_step(
    int t, int b, int tid, int lane, int warp,
    float2 (&X)[3],
    float2 (&h)[3], float2 (&c)[3],
    const float2 (&wr0)[3], const float2 (&wr1)[3],
    const float2 (&wc0)[3], const float2 (&wc1)[3],
    const float2 (&wi0)[3], const float2 (&wi1)[3],
    float mybias, float& Xc, float& Xh,
    const float2* __restrict__ in2, float2* __restrict__ out2,
    float (*sPart)[8][8])
{
    const int  rid = lane & 7;
    const bool lo  = lane < 16;
    const bool b3  = (lane & 8) != 0;
    const bool b2  = (lane & 4) != 0;
    const bool writer = lo ? ((lane & 3) == 0) : ((lane & 7) == 0);
    const int  wrow   = lo ? (((lane >> 3) & 1) * 2 + ((lane >> 2) & 1))
                           : (4 + ((lane >> 3) & 1));

    // x partials for step t+1 (from X = x_{t+1}, loaded 4 steps ago)
    float x4 = 0.0f, x5 = 0.0f;
    #pragma unroll
    for (int j = 0; j < 3; j++) {
        x4 = fmaf(X[j].x, wi0[j].x, fmaf(X[j].y, wi0[j].y, x4));
        x5 = fmaf(X[j].x, wi1[j].x, fmaf(X[j].y, wi1[j].y, x5));
    }

    // refill this slot with x_{t+5}: 4-step latency budget
    {
        const int tp = (t + 5 < T_STEPS) ? t + 5 : T_STEPS - 1;
        const long xbase = (long)tp * BATCH * F2 + (long)b * F2;
        #pragma unroll
        for (int j = 0; j < 3; j++) X[j] = in2[xbase + tid + 256 * j];
    }

    // gate partials: g0=Hc g1=Hh g2=Cc g3=Ch
    float g0 = 0, g1 = 0, g2 = 0, g3 = 0;
    #pragma unroll
    for (int j = 0; j < 3; j++) {
        g0 = fmaf(h[j].x, wr0[j].x, fmaf(h[j].y, wr0[j].y, g0));
        g1 = fmaf(h[j].x, wr1[j].x, fmaf(h[j].y, wr1[j].y, g1));
        g2 = fmaf(c[j].x, wc0[j].x, fmaf(c[j].y, wc0[j].y, g2));
        g3 = fmaf(c[j].x, wc1[j].x, fmaf(c[j].y, wc1[j].y, g3));
    }

    // ---- 6-sum butterfly: 9 SHFL, 5 levels ----
    float rA = __shfl_xor_sync(~0u, lo ? x4 : g0, 16);
    float rB = __shfl_xor_sync(~0u, lo ? x5 : g1, 16);
    float rC = __shfl_xor_sync(~0u, g2, 16);
    float rD = __shfl_xor_sync(~0u, g3, 16);
    if (lo) { g0 += rA; g1 += rB; g2 += rC; g3 += rD; }
    else    { x4 += rA; x5 += rB; }
    float P  = lo ? (b3 ? g2 : g0) : (b3 ? x5 : x4);
    float sP = lo ? (b3 ? g0 : g2) : (b3 ? x4 : x5);
    P += __shfl_xor_sync(~0u, sP, 8);
    float Q  = b3 ? g3 : g1;
    float sQ = b3 ? g1 : g3;
    Q += __shfl_xor_sync(~0u, sQ, 8);
    float R  = lo ? (b2 ? Q : P) : P;
    float sR = lo ? (b2 ? P : Q) : P;
    R += __shfl_xor_sync(~0u, sR, 4);
    R += __shfl_xor_sync(~0u, R, 2);
    R += __shfl_xor_sync(~0u, R, 1);
    // lane holds full warp sum of id: lo -> b3*2+b2 (gates), hi -> 4+b3 (X)

    const int buf = t & 1;
    if (writer) sPart[buf][wrow][warp] = R;
    __syncthreads();

    // ---- tail: reduce 8 cross-warp partials of row rid ----
    float4 q0 = ((const float4*)sPart[buf][rid])[0];
    float4 q1 = ((const float4*)sPart[buf][rid])[1];
    float s = ((q0.x + q0.y) + (q0.z + q0.w))
            + ((q1.x + q1.y) + (q1.z + q1.w)) + mybias;

    float gval;
    if (rid < 4) {
        // 1 - sigmoid(s) = 0.5 - 0.5*tanh(s/2)
        float sg  = fmaf(-0.5f, tanha(0.5f * s), 0.5f);
        float fac = (rid == 0) ? Xc : (rid == 3) ? Xh : 1.0f;
        gval = sg * fac;
    } else {
        gval = s;   // X sums for step t+1
    }
    const float gca = __shfl_sync(~0u, gval, 0);   // (1-sig(Hc))*Xc
    const float ghb = __shfl_sync(~0u, gval, 1);   // (1-sig(Hh))
    const float gcb = __shfl_sync(~0u, gval, 2);   // (1-sig(Cc))
    const float gha = __shfl_sync(~0u, gval, 3);   // (1-sig(Ch))*Xh
    Xc = __shfl_sync(~0u, gval, 4);
    Xh = __shfl_sync(~0u, gval, 5);

    float2* ob = out2 + ((long)t * BATCH + b) * F2;
    #pragma unroll
    for (int j = 0; j < 3; j++) {
        h[j].x = tanha(fmaf(ghb, h[j].x, gha));
        h[j].y = tanha(fmaf(ghb, h[j].y, gha));
        c[j].x = tanha(fmaf(gcb, c[j].x, gca));
        c[j].y = tanha(fmaf(gcb, c[j].y, gca));
        ob[tid + 256 * j] = h[j];
    }
}

// ---------------------------------------------------------------------------
// Fully fused kernel: one CTA per batch element, 256 threads (8 warps).
// 4-slot register input pipeline: slot u holds x_{t+1} for steps t = u mod 4.
// ---------------------------------------------------------------------------
__global__ void __launch_bounds__(256) fused_kernel(
    const float* __restrict__ inputs,
    const float* __restrict__ h0,
    const float* __restrict__ c0,
    const float* __restrict__ Wr,
    const float* __restrict__ br,
    const float* __restrict__ Wc,
    const float* __restrict__ bc,
    const float* __restrict__ Wi,
    const float* __restrict__ bi,
    float* __restrict__ out)
{
    __shared__ float sPart[2][8][8];   // [buf][row][warp]: rows 0-5 used

    const int tid  = threadIdx.x;
    const int b    = blockIdx.x;
    const int warp = tid >> 5;
    const int lane = tid & 31;

    const float2* in2 = (const float2*)inputs;
    const float2* h02 = (const float2*)h0;
    const float2* c02 = (const float2*)c0;
    const float2* Wr2 = (const float2*)Wr;
    const float2* Wc2 = (const float2*)Wc;
    const float2* Wi2 = (const float2*)Wi;
    float2* out2 = (float2*)out;

    float2 h[3], c[3], wr0[3], wr1[3], wc0[3], wc1[3], wi0[3], wi1[3];
    #pragma unroll
    for (int j = 0; j < 3; j++) {
        const int p = tid + 256 * j;
        h[j]   = h02[b * F2 + p];
        c[j]   = c02[b * F2 + p];
        wr0[j] = Wr2[p];        wr1[j] = Wr2[F2 + p];
        wc0[j] = Wc2[p];        wc1[j] = Wc2[F2 + p];
        wi0[j] = Wi2[p];        wi1[j] = Wi2[F2 + p];
    }
    const float br0 = br[0], br1 = br[1];
    const float bc0 = bc[0], bc1 = bc[1];
    const float bi0 = bi[0], bi1 = bi[1];

    const int rid = lane & 7;
    const float mybias = (rid == 0) ? br0 : (rid == 1) ? br1
                       : (rid == 2) ? bc0 : (rid == 3) ? bc1
                       : (rid == 4) ? bi0 : (rid == 5) ? bi1 : 0.0f;

    // zero unused rows so the tail never touches garbage
    if (tid < 16) {
        sPart[0][6][tid & 7] = 0.0f; sPart[0][7][tid & 7] = 0.0f;
        sPart[1][6][tid & 7] = 0.0f; sPart[1][7][tid & 7] = 0.0f;
    }

    // ---- prologue: reduce X0 = Wi.x_0 + bi; fill pipeline x_1..x_4 ----
    float2 X0s[3], X1s[3], X2s[3], X3s[3];
    {
        float v4 = 0.0f, v5 = 0.0f;
        #pragma unroll
        for (int j = 0; j < 3; j++) {
            const int p = tid + 256 * j;
            float2 x0 = in2[(long)b * F2 + p];                       // t=0
            v4 = fmaf(x0.x, wi0[j].x, fmaf(x0.y, wi0[j].y, v4));
            v5 = fmaf(x0.x, wi1[j].x, fmaf(x0.y, wi1[j].y, v5));
            X0s[j] = in2[(long)1 * BATCH * F2 + (long)b * F2 + p];   // t=1
            X1s[j] = in2[(long)2 * BATCH * F2 + (long)b * F2 + p];   // t=2
            X2s[j] = in2[(long)3 * BATCH * F2 + (long)b * F2 + p];   // t=3
            X3s[j] = in2[(long)4 * BATCH * F2 + (long)b * F2 + p];   // t=4
        }
        // 2-sum butterfly for the prologue projection
        const bool lo = lane < 16;
        float k = lo ? v4 : v5;
        float s = lo ? v5 : v4;
        k += __shfl_xor_sync(~0u, s, 16);
        k += __shfl_xor_sync(~0u, k, 8);
        k += __shfl_xor_sync(~0u, k, 4);
        k += __shfl_xor_sync(~0u, k, 2);
        k += __shfl_xor_sync(~0u, k, 1);
        if (lane == 0)  sPart[1][4][warp] = k;
        if (lane == 16) sPart[1][5][warp] = k;
    }
    __syncthreads();
    float Xc, Xh;
    {
        float4 a0 = ((const float4*)sPart[1][4])[0], a1 = ((const float4*)sPart[1][4])[1];
        float4 d0 = ((const float4*)sPart[1][5])[0], d1 = ((const float4*)sPart[1][5])[1];
        Xc = ((a0.x + a0.y) + (a0.z + a0.w)) + ((a1.x + a1.y) + (a1.z + a1.w)) + bi0;
        Xh = ((d0.x + d0.y) + (d0.z + d0.w)) + ((d1.x + d1.y) + (d1.z + d1.w)) + bi1;
    }

    for (int tb = 0; tb < T_STEPS; tb += 4) {
        do_step(tb + 0, b, tid, lane, warp, X0s, h, c,
                wr0, wr1, wc0, wc1, wi0, wi1, mybias, Xc, Xh, in2, out2, sPart);
        do_step(tb + 1, b, tid, lane, warp, X1s, h, c,
                wr0, wr1, wc0, wc1, wi0, wi1, mybias, Xc, Xh, in2, out2, sPart);
        do_step(tb + 2, b, tid, lane, warp, X2s, h, c,
                wr0, wr1, wc0, wc1, wi0, wi1, mybias, Xc, Xh, in2, out2, sPart);
        do_step(tb + 3, b, tid, lane, warp, X3s, h, c,
                wr0, wr1, wc0, wc1, wi0, wi1, mybias, Xc, Xh, in2, out2, sPart);
    }

    // final hT, cT
    const long offH = (long)T_STEPS * BATCH * F2;
    const long offC = offH + (long)BATCH * F2;
    #pragma unroll
    for (int j = 0; j < 3; j++) {
        const int p = tid + 256 * j;
        out2[offH + (long)b * F2 + p] = h[j];
        out2[offC + (long)b * F2 + p] = c[j];
    }
}

extern "C" void kernel_launch(void* const* d_in, const int* in_sizes, int n_in,
                              void* d_out, int out_size)
{
    const float* inputs = (const float*)d_in[0];
    const float* h0     = (const float*)d_in[1];
    const float* c0     = (const float*)d_in[2];
    const float* Wr     = (const float*)d_in[3];
    const float* br     = (const float*)d_in[4];
    const float* Wc     = (const float*)d_in[5];
    const float* bc     = (const float*)d_in[6];
    const float* Wi     = (const float*)d_in[7];
    const float* bi     = (const float*)d_in[8];
    float* out = (float*)d_out;

    fused_kernel<<<BATCH, 256>>>(inputs, h0, c0, Wr, br, Wc, bc, Wi, bi, out);
}

// round 8
// speedup vs baseline: 2.2567x; 1.0625x over previous
#include <cuda_runtime.h>
#include <cstdint>

#define T_STEPS 256
#define BATCH   128
#define KDIM    1536
#define F4      384     // KDIM/4 (float4 units)
#define NTHR    128
#define STAGES  5

// HW tanh: single MUFU op, max rel err ~2^-11.
__device__ __forceinline__ float tanha(float x) {
    float y;
    asm("tanh.approx.f32 %0, %1;" : "=f"(y) : "f"(x));
    return y;
}

__device__ __forceinline__ void cp_async16(uint32_t dst, const void* src) {
    asm volatile("cp.async.cg.shared.global [%0], [%1], 16;" :: "r"(dst), "l"(src));
}
#define CP_COMMIT() asm volatile("cp.async.commit_group;" ::: "memory")
#define CP_WAIT3()  asm volatile("cp.async.wait_group 3;" ::: "memory")

// 12-term dot product (3 float4 each side), 2 accumulator chains.
__device__ __forceinline__ float dot12(const float4* v, const float4* w) {
    float a0 = 0.0f, a1 = 0.0f;
    #pragma unroll
    for (int j = 0; j < 3; j++) {
        a0 = fmaf(v[j].x, w[j].x, fmaf(v[j].y, w[j].y, a0));
        a1 = fmaf(v[j].z, w[j].z, fmaf(v[j].w, w[j].w, a1));
    }
    return a0 + a1;
}

// ---------------------------------------------------------------------------
// Fully fused kernel: one CTA per batch element, 128 threads (4 warps, one
// per SMSP). Thread owns 12 CONTIGUOUS floats (3 float4) of the 1536-dim
// state: all state/weight/output traffic is 128-bit. Input x streams through
// a 5-stage cp.async SMEM pipeline (4-step latency budget, no barrier needed:
// each thread copies and reads its own 48B). Per step: 6-sum warp butterfly
// (4 gates of step t + 2 input sums of step t+1), one barrier, 4-wide tail.
// ---------------------------------------------------------------------------
__global__ void __launch_bounds__(NTHR) fused_kernel(
    const float* __restrict__ inputs,
    const float* __restrict__ h0,
    const float* __restrict__ c0,
    const float* __restrict__ Wr,
    const float* __restrict__ br,
    const float* __restrict__ Wc,
    const float* __restrict__ bc,
    const float* __restrict__ Wi,
    const float* __restrict__ bi,
    float* __restrict__ out)
{
    __shared__ float  sPart[2][8][4];        // [buf][row][warp]; rows 0-5 used
    __shared__ float4 sX[STAGES][F4];        // 5 x 6KB input stages

    const int tid  = threadIdx.x;
    const int b    = blockIdx.x;
    const int warp = tid >> 5;
    const int lane = tid & 31;

    const float4* in4 = (const float4*)inputs;
    const float4* Wr4 = (const float4*)Wr;
    const float4* Wc4 = (const float4*)Wc;
    const float4* Wi4 = (const float4*)Wi;
    float4* out4 = (float4*)out;

    float4 h[3], c[3], wr0[3], wr1[3], wc0[3], wc1[3], wi0[3], wi1[3];
    #pragma unroll
    for (int j = 0; j < 3; j++) {
        const int p = 3 * tid + j;
        h[j]   = ((const float4*)h0)[b * F4 + p];
        c[j]   = ((const float4*)c0)[b * F4 + p];
        wr0[j] = Wr4[p];        wr1[j] = Wr4[F4 + p];
        wc0[j] = Wc4[p];        wc1[j] = Wc4[F4 + p];
        wi0[j] = Wi4[p];        wi1[j] = Wi4[F4 + p];
    }
    const float br0 = br[0], br1 = br[1];
    const float bc0 = bc[0], bc1 = bc[1];
    const float bi0 = bi[0], bi1 = bi[1];

    const int rid = lane & 7;
    const float mybias = (rid == 0) ? br0 : (rid == 1) ? br1
                       : (rid == 2) ? bc0 : (rid == 3) ? bc1
                       : (rid == 4) ? bi0 : (rid == 5) ? bi1 : 0.0f;

    // lane roles for the 6-sum butterfly
    const bool lo  = lane < 16;
    const bool b3  = (lane & 8) != 0;
    const bool b2  = (lane & 4) != 0;
    const bool writer = lo ? ((lane & 3) == 0) : ((lane & 7) == 0);
    const int  wrow   = lo ? (((lane >> 3) & 1) * 2 + ((lane >> 2) & 1))
                           : (4 + ((lane >> 3) & 1));

    // zero unused tail rows (6,7) in both buffers
    if (tid < 16) {
        const int bf = tid >> 3, r = 6 + ((tid >> 2) & 1), col = tid & 3;
        sPart[bf][r][col] = 0.0f;
    }

    const uint32_t sx_base = (uint32_t)__cvta_generic_to_shared(&sX[0][0]);
    const uint32_t my_off  = (uint32_t)(3 * tid) * 16u;

    // ---- prologue: X0 projection; start cp.async pipeline for x_1..x_4 ----
    {
        float v4 = 0.0f, v5 = 0.0f;
        float4 x0[3];
        #pragma unroll
        for (int j = 0; j < 3; j++)
            x0[j] = in4[(long)b * F4 + 3 * tid + j];
        v4 = dot12(x0, wi0);
        v5 = dot12(x0, wi1);

        // stages 1..4 <- x_1..x_4 (4 commit groups, in order)
        #pragma unroll
        for (int s = 1; s <= 4; s++) {
            const float4* src = in4 + (long)s * BATCH * F4 + (long)b * F4 + 3 * tid;
            const uint32_t dst = sx_base + (uint32_t)s * (F4 * 16u) + my_off;
            cp_async16(dst,      src);
            cp_async16(dst + 16, src + 1);
            cp_async16(dst + 32, src + 2);
            CP_COMMIT();
        }

        // 2-sum butterfly for the prologue projection
        float k = lo ? v4 : v5;
        float s_ = lo ? v5 : v4;
        k += __shfl_xor_sync(~0u, s_, 16);
        k += __shfl_xor_sync(~0u, k, 8);
        k += __shfl_xor_sync(~0u, k, 4);
        k += __shfl_xor_sync(~0u, k, 2);
        k += __shfl_xor_sync(~0u, k, 1);
        if (lane == 0)  sPart[1][4][warp] = k;
        if (lane == 16) sPart[1][5][warp] = k;
    }
    __syncthreads();
    float Xc, Xh;
    {
        float4 q4 = *(const float4*)sPart[1][4];
        float4 q5 = *(const float4*)sPart[1][5];
        Xc = (q4.x + q4.y) + (q4.z + q4.w) + bi0;
        Xh = (q5.x + q5.y) + (q5.z + q5.w) + bi1;
    }

    int sc = 1;   // stage holding x_{t+1}
    int sw = 0;   // stage to fill with x_{t+5}

    for (int t = 0; t < T_STEPS; t++) {
        // ---- consume x_{t+1} from the pipeline (own 48B; no barrier) ----
        CP_WAIT3();
        float4 xr[3];
        {
            const float4* xs = &sX[sc][3 * tid];
            xr[0] = xs[0]; xr[1] = xs[1]; xr[2] = xs[2];
        }
        float x4 = dot12(xr, wi0);
        float x5 = dot12(xr, wi1);

        // ---- refill stage sw with x_{min(t+5,255)} ----
        {
            const int tp = (t + 5 < T_STEPS) ? t + 5 : T_STEPS - 1;
            const float4* src = in4 + (long)tp * BATCH * F4 + (long)b * F4 + 3 * tid;
            const uint32_t dst = sx_base + (uint32_t)sw * (F4 * 16u) + my_off;
            cp_async16(dst,      src);
            cp_async16(dst + 16, src + 1);
            cp_async16(dst + 32, src + 2);
            CP_COMMIT();
        }

        // ---- gate partials: g0=Hc g1=Hh g2=Cc g3=Ch ----
        float g0 = dot12(h, wr0);
        float g1 = dot12(h, wr1);
        float g2 = dot12(c, wc0);
        float g3 = dot12(c, wc1);

        // ---- 6-sum butterfly: 9 SHFL, 5 levels ----
        float rA = __shfl_xor_sync(~0u, lo ? x4 : g0, 16);
        float rB = __shfl_xor_sync(~0u, lo ? x5 : g1, 16);
        float rC = __shfl_xor_sync(~0u, g2, 16);
        float rD = __shfl_xor_sync(~0u, g3, 16);
        if (lo) { g0 += rA; g1 += rB; g2 += rC; g3 += rD; }
        else    { x4 += rA; x5 += rB; }
        float P  = lo ? (b3 ? g2 : g0) : (b3 ? x5 : x4);
        float sP = lo ? (b3 ? g0 : g2) : (b3 ? x4 : x5);
        P += __shfl_xor_sync(~0u, sP, 8);
        float Q  = b3 ? g3 : g1;
        float sQ = b3 ? g1 : g3;
        Q += __shfl_xor_sync(~0u, sQ, 8);
        float R  = lo ? (b2 ? Q : P) : P;
        float sR = lo ? (b2 ? P : Q) : P;
        R += __shfl_xor_sync(~0u, sR, 4);
        R += __shfl_xor_sync(~0u, R, 2);
        R += __shfl_xor_sync(~0u, R, 1);

        const int buf = t & 1;
        if (writer) sPart[buf][wrow][warp] = R;
        __syncthreads();

        // ---- tail: 4 cross-warp partials of row rid (one LDS.128) ----
        float4 q = *(const float4*)sPart[buf][rid];
        float s = (q.x + q.y) + (q.z + q.w) + mybias;

        float gval;
        if (rid < 4) {
            // 1 - sigmoid(s) = 0.5 - 0.5*tanh(s/2)
            float sg  = fmaf(-0.5f, tanha(0.5f * s), 0.5f);
            float fac = (rid == 0) ? Xc : (rid == 3) ? Xh : 1.0f;
            gval = sg * fac;
        } else {
            gval = s;   // X sums for step t+1
        }
        const float gca = __shfl_sync(~0u, gval, 0);   // (1-sig(Hc))*Xc
        const float ghb = __shfl_sync(~0u, gval, 1);   // (1-sig(Hh))
        const float gcb = __shfl_sync(~0u, gval, 2);   // (1-sig(Cc))
        const float gha = __shfl_sync(~0u, gval, 3);   // (1-sig(Ch))*Xh
        Xc = __shfl_sync(~0u, gval, 4);
        Xh = __shfl_sync(~0u, gval, 5);

        float4* ob = out4 + ((long)t * BATCH + b) * F4 + 3 * tid;
        #pragma unroll
        for (int j = 0; j < 3; j++) {
            h[j].x = tanha(fmaf(ghb, h[j].x, gha));
            h[j].y = tanha(fmaf(ghb, h[j].y, gha));
            h[j].z = tanha(fmaf(ghb, h[j].z, gha));
            h[j].w = tanha(fmaf(ghb, h[j].w, gha));
            c[j].x = tanha(fmaf(gcb, c[j].x, gca));
            c[j].y = tanha(fmaf(gcb, c[j].y, gca));
            c[j].z = tanha(fmaf(gcb, c[j].z, gca));
            c[j].w = tanha(fmaf(gcb, c[j].w, gca));
            ob[j] = h[j];
        }

        sc = (sc == STAGES - 1) ? 0 : sc + 1;
        sw = (sw == STAGES - 1) ? 0 : sw + 1;
    }

    // final hT, cT
    const long offH = (long)T_STEPS * BATCH * F4;
    const long offC = offH + (long)BATCH * F4;
    #pragma unroll
    for (int j = 0; j < 3; j++) {
        out4[offH + (long)b * F4 + 3 * tid + j] = h[j];
        out4[offC + (long)b * F4 + 3 * tid + j] = c[j];
    }
}

extern "C" void kernel_launch(void* const* d_in, const int* in_sizes, int n_in,
                              void* d_out, int out_size)
{
    const float* inputs = (const float*)d_in[0];
    const float* h0     = (const float*)d_in[1];
    const float* c0     = (const float*)d_in[2];
    const float* Wr     = (const float*)d_in[3];
    const float* br     = (const float*)d_in[4];
    const float* Wc     = (const float*)d_in[5];
    const float* bc     = (const float*)d_in[6];
    const float* Wi     = (const float*)d_in[7];
    const float* bi     = (const float*)d_in[8];
    float* out = (float*)d_out;

    fused_kernel<<<BATCH, NTHR>>>(inputs, h0, c0, Wr, br, Wc, bc, Wi, bi, out);
}

// round 9
// speedup vs baseline: 2.6070x; 1.1552x over previous
#include <cuda_runtime.h>
#include <cstdint>

#define T_STEPS 256
#define BATCH   128
#define KDIM    1536
#define F4      384     // KDIM/4 (float4 units)
#define NTHR    128
#define STAGES  5

// HW tanh: single MUFU op, max rel err ~2^-11.
__device__ __forceinline__ float tanha(float x) {
    float y;
    asm("tanh.approx.f32 %0, %1;" : "=f"(y) : "f"(x));
    return y;
}

__device__ __forceinline__ void cp_async16(uint32_t dst, const void* src) {
    asm volatile("cp.async.cg.shared.global [%0], [%1], 16;" :: "r"(dst), "l"(src));
}
#define CP_COMMIT() asm volatile("cp.async.commit_group;" ::: "memory")
#define CP_WAIT3()  asm volatile("cp.async.wait_group 3;" ::: "memory")

// 12-term dot product (3 float4 each side), 2 accumulator chains.
__device__ __forceinline__ float dot12(const float4* v, const float4* w) {
    float a0 = 0.0f, a1 = 0.0f;
    #pragma unroll
    for (int j = 0; j < 3; j++) {
        a0 = fmaf(v[j].x, w[j].x, fmaf(v[j].y, w[j].y, a0));
        a1 = fmaf(v[j].z, w[j].z, fmaf(v[j].w, w[j].w, a1));
    }
    return a0 + a1;
}

// ---------------------------------------------------------------------------
// Fully fused kernel: one CTA per batch element, 128 threads (4 warps, one
// per SMSP). Thread owns 3 STRIDED float4 slots (index tid + 128*j) of the
// 1536-dim state: every warp memory op covers 512B contiguous (4 L1 lines,
// minimum), SMEM reads are conflict-free. Input x streams through a 5-stage
// cp.async SMEM pipeline (4-step latency budget; each thread copies and reads
// its own slots, no barrier for x). Per step: 6-sum warp butterfly (4 gates
// of step t + 2 input sums of step t+1), one barrier, 4-wide tail.
// ---------------------------------------------------------------------------
__global__ void __launch_bounds__(NTHR) fused_kernel(
    const float* __restrict__ inputs,
    const float* __restrict__ h0,
    const float* __restrict__ c0,
    const float* __restrict__ Wr,
    const float* __restrict__ br,
    const float* __restrict__ Wc,
    const float* __restrict__ bc,
    const float* __restrict__ Wi,
    const float* __restrict__ bi,
    float* __restrict__ out)
{
    __shared__ float  sPart[2][8][4];        // [buf][row][warp]; rows 0-5 used
    __shared__ float4 sX[STAGES][F4];        // 5 x 6KB input stages

    const int tid  = threadIdx.x;
    const int b    = blockIdx.x;
    const int warp = tid >> 5;
    const int lane = tid & 31;

    const float4* in4 = (const float4*)inputs;
    const float4* Wr4 = (const float4*)Wr;
    const float4* Wc4 = (const float4*)Wc;
    const float4* Wi4 = (const float4*)Wi;
    float4* out4 = (float4*)out;

    float4 h[3], c[3], wr0[3], wr1[3], wc0[3], wc1[3], wi0[3], wi1[3];
    #pragma unroll
    for (int j = 0; j < 3; j++) {
        const int p = tid + 128 * j;           // strided ownership: coalesced
        h[j]   = ((const float4*)h0)[b * F4 + p];
        c[j]   = ((const float4*)c0)[b * F4 + p];
        wr0[j] = Wr4[p];        wr1[j] = Wr4[F4 + p];
        wc0[j] = Wc4[p];        wc1[j] = Wc4[F4 + p];
        wi0[j] = Wi4[p];        wi1[j] = Wi4[F4 + p];
    }
    const float br0 = br[0], br1 = br[1];
    const float bc0 = bc[0], bc1 = bc[1];
    const float bi0 = bi[0], bi1 = bi[1];

    const int rid = lane & 7;
    const float mybias = (rid == 0) ? br0 : (rid == 1) ? br1
                       : (rid == 2) ? bc0 : (rid == 3) ? bc1
                       : (rid == 4) ? bi0 : (rid == 5) ? bi1 : 0.0f;

    // lane roles for the 6-sum butterfly
    const bool lo  = lane < 16;
    const bool b3  = (lane & 8) != 0;
    const bool b2  = (lane & 4) != 0;
    const bool writer = lo ? ((lane & 3) == 0) : ((lane & 7) == 0);
    const int  wrow   = lo ? (((lane >> 3) & 1) * 2 + ((lane >> 2) & 1))
                           : (4 + ((lane >> 3) & 1));

    // zero unused tail rows (6,7) in both buffers
    if (tid < 16) {
        const int bf = tid >> 3, r = 6 + ((tid >> 2) & 1), col = tid & 3;
        sPart[bf][r][col] = 0.0f;
    }

    const uint32_t sx_base = (uint32_t)__cvta_generic_to_shared(&sX[0][0]);

    // ---- prologue: X0 projection; start cp.async pipeline for x_1..x_4 ----
    {
        float4 x0[3];
        #pragma unroll
        for (int j = 0; j < 3; j++)
            x0[j] = in4[(long)b * F4 + tid + 128 * j];
        float v4 = dot12(x0, wi0);
        float v5 = dot12(x0, wi1);

        // stages 1..4 <- x_1..x_4 (4 commit groups, in order)
        #pragma unroll
        for (int s = 1; s <= 4; s++) {
            const float4* src = in4 + (long)s * BATCH * F4 + (long)b * F4;
            const uint32_t dst = sx_base + (uint32_t)s * (F4 * 16u);
            #pragma unroll
            for (int j = 0; j < 3; j++)
                cp_async16(dst + (uint32_t)(tid + 128 * j) * 16u, src + tid + 128 * j);
            CP_COMMIT();
        }

        // 2-sum butterfly for the prologue projection
        float k  = lo ? v4 : v5;
        float s_ = lo ? v5 : v4;
        k += __shfl_xor_sync(~0u, s_, 16);
        k += __shfl_xor_sync(~0u, k, 8);
        k += __shfl_xor_sync(~0u, k, 4);
        k += __shfl_xor_sync(~0u, k, 2);
        k += __shfl_xor_sync(~0u, k, 1);
        if (lane == 0)  sPart[1][4][warp] = k;
        if (lane == 16) sPart[1][5][warp] = k;
    }
    __syncthreads();
    float Xc, Xh;
    {
        float4 q4 = *(const float4*)sPart[1][4];
        float4 q5 = *(const float4*)sPart[1][5];
        Xc = (q4.x + q4.y) + (q4.z + q4.w) + bi0;
        Xh = (q5.x + q5.y) + (q5.z + q5.w) + bi1;
    }

    int sc = 1;   // stage holding x_{t+1}
    int sw = 0;   // stage to fill with x_{t+5}

    for (int t = 0; t < T_STEPS; t++) {
        // ---- consume x_{t+1} from the pipeline (own slots; no barrier) ----
        CP_WAIT3();
        float4 xr[3];
        {
            const float4* xs = &sX[sc][0];
            xr[0] = xs[tid]; xr[1] = xs[tid + 128]; xr[2] = xs[tid + 256];
        }
        float x4 = dot12(xr, wi0);
        float x5 = dot12(xr, wi1);

        // ---- refill stage sw with x_{min(t+5,255)} ----
        {
            const int tp = (t + 5 < T_STEPS) ? t + 5 : T_STEPS - 1;
            const float4* src = in4 + (long)tp * BATCH * F4 + (long)b * F4;
            const uint32_t dst = sx_base + (uint32_t)sw * (F4 * 16u);
            #pragma unroll
            for (int j = 0; j < 3; j++)
                cp_async16(dst + (uint32_t)(tid + 128 * j) * 16u, src + tid + 128 * j);
            CP_COMMIT();
        }

        // ---- gate partials: g0=Hc g1=Hh g2=Cc g3=Ch ----
        float g0 = dot12(h, wr0);
        float g1 = dot12(h, wr1);
        float g2 = dot12(c, wc0);
        float g3 = dot12(c, wc1);

        // ---- 6-sum butterfly: 9 SHFL, 5 levels ----
        float rA = __shfl_xor_sync(~0u, lo ? x4 : g0, 16);
        float rB = __shfl_xor_sync(~0u, lo ? x5 : g1, 16);
        float rC = __shfl_xor_sync(~0u, g2, 16);
        float rD = __shfl_xor_sync(~0u, g3, 16);
        if (lo) { g0 += rA; g1 += rB; g2 += rC; g3 += rD; }
        else    { x4 += rA; x5 += rB; }
        float P  = lo ? (b3 ? g2 : g0) : (b3 ? x5 : x4);
        float sP = lo ? (b3 ? g0 : g2) : (b3 ? x4 : x5);
        P += __shfl_xor_sync(~0u, sP, 8);
        float Q  = b3 ? g3 : g1;
        float sQ = b3 ? g1 : g3;
        Q += __shfl_xor_sync(~0u, sQ, 8);
        float R  = lo ? (b2 ? Q : P) : P;
        float sR = lo ? (b2 ? P : Q) : P;
        R += __shfl_xor_sync(~0u, sR, 4);
        R += __shfl_xor_sync(~0u, R, 2);
        R += __shfl_xor_sync(~0u, R, 1);

        const int buf = t & 1;
        if (writer) sPart[buf][wrow][warp] = R;
        __syncthreads();

        // ---- tail: 4 cross-warp partials of row rid (one LDS.128) ----
        float4 q = *(const float4*)sPart[buf][rid];
        float s = (q.x + q.y) + (q.z + q.w) + mybias;

        float gval;
        if (rid < 4) {
            // 1 - sigmoid(s) = 0.5 - 0.5*tanh(s/2)
            float sg  = fmaf(-0.5f, tanha(0.5f * s), 0.5f);
            float fac = (rid == 0) ? Xc : (rid == 3) ? Xh : 1.0f;
            gval = sg * fac;
        } else {
            gval = s;   // X sums for step t+1
        }
        const float gca = __shfl_sync(~0u, gval, 0);   // (1-sig(Hc))*Xc
        const float ghb = __shfl_sync(~0u, gval, 1);   // (1-sig(Hh))
        const float gcb = __shfl_sync(~0u, gval, 2);   // (1-sig(Cc))
        const float gha = __shfl_sync(~0u, gval, 3);   // (1-sig(Ch))*Xh
        Xc = __shfl_sync(~0u, gval, 4);
        Xh = __shfl_sync(~0u, gval, 5);

        float4* ob = out4 + ((long)t * BATCH + b) * F4;
        #pragma unroll
        for (int j = 0; j < 3; j++) {
            h[j].x = tanha(fmaf(ghb, h[j].x, gha));
            h[j].y = tanha(fmaf(ghb, h[j].y, gha));
            h[j].z = tanha(fmaf(ghb, h[j].z, gha));
            h[j].w = tanha(fmaf(ghb, h[j].w, gha));
            c[j].x = tanha(fmaf(gcb, c[j].x, gca));
            c[j].y = tanha(fmaf(gcb, c[j].y, gca));
            c[j].z = tanha(fmaf(gcb, c[j].z, gca));
            c[j].w = tanha(fmaf(gcb, c[j].w, gca));
            ob[tid + 128 * j] = h[j];
        }

        sc = (sc == STAGES - 1) ? 0 : sc + 1;
        sw = (sw == STAGES - 1) ? 0 : sw + 1;
    }

    // final hT, cT
    const long offH = (long)T_STEPS * BATCH * F4;
    const long offC = offH + (long)BATCH * F4;
    #pragma unroll
    for (int j = 0; j < 3; j++) {
        out4[offH + (long)b * F4 + tid + 128 * j] = h[j];
        out4[offC + (long)b * F4 + tid + 128 * j] = c[j];
    }
}

extern "C" void kernel_launch(void* const* d_in, const int* in_sizes, int n_in,
                              void* d_out, int out_size)
{
    const float* inputs = (const float*)d_in[0];
    const float* h0     = (const float*)d_in[1];
    const float* c0     = (const float*)d_in[2];
    const float* Wr     = (const float*)d_in[3];
    const float* br     = (const float*)d_in[4];
    const float* Wc     = (const float*)d_in[5];
    const float* bc     = (const float*)d_in[6];
    const float* Wi     = (const float*)d_in[7];
    const float* bi     = (const float*)d_in[8];
    float* out = (float*)d_out;

    fused_kernel<<<BATCH, NTHR>>>(inputs, h0, c0, Wr, br, Wc, bc, Wi, bi, out);
}

// round 10
// speedup vs baseline: 2.7924x; 1.0711x over previous
#include <cuda_runtime.h>
#include <cstdint>

#define T_STEPS 256
#define BATCH   128
#define KDIM    1536
#define F4      384     // KDIM/4 (float4 units)
#define NTHR    128
#define STAGES  4
#define STAGE_B 6144u   // F4 * 16 bytes

// HW tanh: single MUFU op, max rel err ~2^-11.
__device__ __forceinline__ float tanha(float x) {
    float y;
    asm("tanh.approx.f32 %0, %1;" : "=f"(y) : "f"(x));
    return y;
}

__device__ __forceinline__ void cp_async16(uint32_t dst, const void* src) {
    asm volatile("cp.async.cg.shared.global [%0], [%1], 16;" :: "r"(dst), "l"(src));
}
#define CP_COMMIT() asm volatile("cp.async.commit_group;" ::: "memory")
#define CP_WAIT2()  asm volatile("cp.async.wait_group 2;" ::: "memory")

// packed f32x2 fma
__device__ __forceinline__ void ffma2(unsigned long long& acc,
                                      unsigned long long a,
                                      unsigned long long b) {
    asm("fma.rn.f32x2 %0, %1, %2, %0;" : "+l"(acc) : "l"(a), "l"(b));
}
__device__ __forceinline__ float2 unpack2(unsigned long long v) {
    float2 f;
    asm("mov.b64 {%0, %1}, %2;" : "=f"(f.x), "=f"(f.y) : "l"(v));
    return f;
}

// 12-term dot product (3 float4 each side), 2 accumulator chains.
__device__ __forceinline__ float dot12(const float4* v, const float4* w) {
    float a0 = 0.0f, a1 = 0.0f;
    #pragma unroll
    for (int j = 0; j < 3; j++) {
        a0 = fmaf(v[j].x, w[j].x, fmaf(v[j].y, w[j].y, a0));
        a1 = fmaf(v[j].z, w[j].z, fmaf(v[j].w, w[j].w, a1));
    }
    return a0 + a1;
}

// ---------------------------------------------------------------------------
// Fully fused kernel: one CTA per batch element, 128 threads (4 warps).
// Strided float4 ownership (tid + 128*j): all gmem ops fully coalesced.
// 4-stage cp.async SMEM input ring, loop unrolled by 4 so stage indices,
// buffer parity and all SMEM addresses are compile-time constants; gmem
// pointers are strength-reduced (one add per step). Per step: 6-sum warp
// butterfly (4 gates of t + 2 input sums of t+1, x-dots in FFMA2), one
// barrier, 4-wide tail, 6 broadcasts, tanh.approx update.
// ---------------------------------------------------------------------------
__global__ void __launch_bounds__(NTHR) fused_kernel(
    const float* __restrict__ inputs,
    const float* __restrict__ h0,
    const float* __restrict__ c0,
    const float* __restrict__ Wr,
    const float* __restrict__ br,
    const float* __restrict__ Wc,
    const float* __restrict__ bc,
    const float* __restrict__ Wi,
    const float* __restrict__ bi,
    float* __restrict__ out)
{
    __shared__ float      sPart[2][8][4];     // [buf][row][warp]; rows 0-5 used
    __shared__ ulonglong2 sX[STAGES * F4];    // 4 x 6KB input stages (packed)

    const int tid  = threadIdx.x;
    const int b    = blockIdx.x;
    const int warp = tid >> 5;
    const int lane = tid & 31;

    const float4*     in4  = (const float4*)inputs;
    const float4*     Wr4  = (const float4*)Wr;
    const float4*     Wc4  = (const float4*)Wc;
    const ulonglong2* Wi2  = (const ulonglong2*)Wi;
    float4* out4 = (float4*)out;

    float4 h[3], c[3], wr0[3], wr1[3], wc0[3], wc1[3];
    ulonglong2 wi0p[3], wi1p[3];
    #pragma unroll
    for (int j = 0; j < 3; j++) {
        const int p = tid + 128 * j;           // strided ownership: coalesced
        h[j]    = ((const float4*)h0)[b * F4 + p];
        c[j]    = ((const float4*)c0)[b * F4 + p];
        wr0[j]  = Wr4[p];        wr1[j]  = Wr4[F4 + p];
        wc0[j]  = Wc4[p];        wc1[j]  = Wc4[F4 + p];
        wi0p[j] = Wi2[p];        wi1p[j] = Wi2[F4 + p];
    }
    const float br0 = br[0], br1 = br[1];
    const float bc0 = bc[0], bc1 = bc[1];
    const float bi0 = bi[0], bi1 = bi[1];

    const int rid = lane & 7;
    const float mybias = (rid == 0) ? br0 : (rid == 1) ? br1
                       : (rid == 2) ? bc0 : (rid == 3) ? bc1
                       : (rid == 4) ? bi0 : (rid == 5) ? bi1 : 0.0f;

    // lane roles for the 6-sum butterfly
    const bool lo  = lane < 16;
    const bool b3  = (lane & 8) != 0;
    const bool b2  = (lane & 4) != 0;
    const bool writer = lo ? ((lane & 3) == 0) : ((lane & 7) == 0);
    const int  wrow   = lo ? (((lane >> 3) & 1) * 2 + ((lane >> 2) & 1))
                           : (4 + ((lane >> 3) & 1));

    // zero unused tail rows (6,7) in both buffers
    if (tid < 16) {
        const int bf = tid >> 3, r = 6 + ((tid >> 2) & 1), col = tid & 3;
        sPart[bf][r][col] = 0.0f;
    }

    const uint32_t sx_tid =
        (uint32_t)__cvta_generic_to_shared(&sX[0]) + (uint32_t)tid * 16u;
    const ulonglong2* sXu = &sX[0];

    // ---- prologue: X0 projection; fill stages 1..3 with x_1..x_3 ----
    {
        float4 x0[3];
        #pragma unroll
        for (int j = 0; j < 3; j++)
            x0[j] = in4[(long)b * F4 + tid + 128 * j];
        float4 wi0f[3], wi1f[3];
        #pragma unroll
        for (int j = 0; j < 3; j++) {
            wi0f[j] = *(const float4*)&wi0p[j];
            wi1f[j] = *(const float4*)&wi1p[j];
        }
        float v4 = dot12(x0, wi0f);
        float v5 = dot12(x0, wi1f);

        #pragma unroll
        for (int s = 1; s <= 3; s++) {
            const float4* src = in4 + (long)s * BATCH * F4 + (long)b * F4 + tid;
            const uint32_t dst = sx_tid + (uint32_t)s * STAGE_B;
            cp_async16(dst,         src);
            cp_async16(dst + 2048u, src + 128);
            cp_async16(dst + 4096u, src + 256);
            CP_COMMIT();
        }

        float k  = lo ? v4 : v5;
        float s_ = lo ? v5 : v4;
        k += __shfl_xor_sync(~0u, s_, 16);
        k += __shfl_xor_sync(~0u, k, 8);
        k += __shfl_xor_sync(~0u, k, 4);
        k += __shfl_xor_sync(~0u, k, 2);
        k += __shfl_xor_sync(~0u, k, 1);
        if (lane == 0)  sPart[1][4][warp] = k;
        if (lane == 16) sPart[1][5][warp] = k;
    }
    __syncthreads();
    float Xc, Xh;
    {
        float4 q4 = *(const float4*)sPart[1][4];
        float4 q5 = *(const float4*)sPart[1][5];
        Xc = (q4.x + q4.y) + (q4.z + q4.w) + bi0;
        Xh = (q5.x + q5.y) + (q5.z + q5.w) + bi1;
    }

    // strength-reduced pointers
    const float4* srcp = in4 + (long)4 * BATCH * F4 + (long)b * F4 + tid; // x_{t+4}
    float4*       outp = out4 + (long)b * F4 + tid;

#define DO_STEP(SC, SW, BUF, SRC)                                              \
    {                                                                          \
        CP_WAIT2();                                                            \
        const ulonglong2* xs = sXu + (SC) * F4 + tid;                          \
        ulonglong2 x0 = xs[0], x1 = xs[128], x2 = xs[256];                     \
        {   /* refill stage SW with x from SRC */                              \
            const uint32_t dst = sx_tid + (uint32_t)(SW) * STAGE_B;            \
            cp_async16(dst,         (SRC));                                    \
            cp_async16(dst + 2048u, (SRC) + 128);                              \
            cp_async16(dst + 4096u, (SRC) + 256);                              \
            CP_COMMIT();                                                       \
        }                                                                      \
        /* x-projection dots for t+1: packed FFMA2 */                          \
        unsigned long long a0 = 0ull, a1 = 0ull, q0_ = 0ull, q1_ = 0ull;       \
        ffma2(a0, x0.x, wi0p[0].x); ffma2(a1, x0.y, wi0p[0].y);                \
        ffma2(q0_, x0.x, wi1p[0].x); ffma2(q1_, x0.y, wi1p[0].y);              \
        ffma2(a0, x1.x, wi0p[1].x); ffma2(a1, x1.y, wi0p[1].y);                \
        ffma2(q0_, x1.x, wi1p[1].x); ffma2(q1_, x1.y, wi1p[1].y);              \
        ffma2(a0, x2.x, wi0p[2].x); ffma2(a1, x2.y, wi0p[2].y);                \
        ffma2(q0_, x2.x, wi1p[2].x); ffma2(q1_, x2.y, wi1p[2].y);              \
        float2 pa0 = unpack2(a0), pa1 = unpack2(a1);                           \
        float2 pb0 = unpack2(q0_), pb1 = unpack2(q1_);                         \
        float x4 = (pa0.x + pa0.y) + (pa1.x + pa1.y);                          \
        float x5 = (pb0.x + pb0.y) + (pb1.x + pb1.y);                          \
        /* gate dots */                                                        \
        float g0 = dot12(h, wr0), g1 = dot12(h, wr1);                          \
        float g2 = dot12(c, wc0), g3 = dot12(c, wc1);                          \
        /* 6-sum butterfly: 9 SHFL, 5 levels */                                \
        float rA = __shfl_xor_sync(~0u, lo ? x4 : g0, 16);                     \
        float rB = __shfl_xor_sync(~0u, lo ? x5 : g1, 16);                     \
        float rC = __shfl_xor_sync(~0u, g2, 16);                               \
        float rD = __shfl_xor_sync(~0u, g3, 16);                               \
        if (lo) { g0 += rA; g1 += rB; g2 += rC; g3 += rD; }                    \
        else    { x4 += rA; x5 += rB; }                                        \
        float P  = lo ? (b3 ? g2 : g0) : (b3 ? x5 : x4);                       \
        float sP = lo ? (b3 ? g0 : g2) : (b3 ? x4 : x5);                       \
        P += __shfl_xor_sync(~0u, sP, 8);                                      \
        float Q  = b3 ? g3 : g1;                                               \
        float sQ = b3 ? g1 : g3;                                               \
        Q += __shfl_xor_sync(~0u, sQ, 8);                                      \
        float R  = lo ? (b2 ? Q : P) : P;                                      \
        float sR = lo ? (b2 ? P : Q) : P;                                      \
        R += __shfl_xor_sync(~0u, sR, 4);                                      \
        R += __shfl_xor_sync(~0u, R, 2);                                       \
        R += __shfl_xor_sync(~0u, R, 1);                                       \
        if (writer) sPart[BUF][wrow][warp] = R;                                \
        __syncthreads();                                                       \
        float4 qv = *(const float4*)sPart[BUF][rid];                           \
        float s = (qv.x + qv.y) + (qv.z + qv.w) + mybias;                      \
        float gval;                                                            \
        if (rid < 4) {                                                         \
            float sg  = fmaf(-0.5f, tanha(0.5f * s), 0.5f);                    \
            float fac = (rid == 0) ? Xc : (rid == 3) ? Xh : 1.0f;              \
            gval = sg * fac;                                                   \
        } else {                                                               \
            gval = s;                                                          \
        }                                                                      \
        const float gca = __shfl_sync(~0u, gval, 0);                           \
        const float ghb = __shfl_sync(~0u, gval, 1);                           \
        const float gcb = __shfl_sync(~0u, gval, 2);                           \
        const float gha = __shfl_sync(~0u, gval, 3);                           \
        Xc = __shfl_sync(~0u, gval, 4);                                        \
        Xh = __shfl_sync(~0u, gval, 5);                                        \
        _Pragma("unroll")                                                      \
        for (int j = 0; j < 3; j++) {                                          \
            h[j].x = tanha(fmaf(ghb, h[j].x, gha));                            \
            h[j].y = tanha(fmaf(ghb, h[j].y, gha));                            \
            h[j].z = tanha(fmaf(ghb, h[j].z, gha));                            \
            h[j].w = tanha(fmaf(ghb, h[j].w, gha));                            \
            c[j].x = tanha(fmaf(gcb, c[j].x, gca));                            \
            c[j].y = tanha(fmaf(gcb, c[j].y, gca));                            \
            c[j].z = tanha(fmaf(gcb, c[j].z, gca));                            \
            c[j].w = tanha(fmaf(gcb, c[j].w, gca));                            \
            outp[128 * j] = h[j];                                              \
        }                                                                      \
        outp += BATCH * F4;                                                    \
    }

    // main loop: 252 steps, unrolled by 4 (static stages / buffer parity)
    for (int tb = 0; tb < 252; tb += 4) {
        DO_STEP(1, 0, 0, srcp); srcp += BATCH * F4;
        DO_STEP(2, 1, 1, srcp); srcp += BATCH * F4;
        DO_STEP(3, 2, 0, srcp); srcp += BATCH * F4;
        DO_STEP(0, 3, 1, srcp); srcp += BATCH * F4;
    }
    // tail: steps 252..255, refill source clamped to x_255
    {
        const float4* srcL = in4 + (long)(T_STEPS - 1) * BATCH * F4
                           + (long)b * F4 + tid;
        DO_STEP(1, 0, 0, srcL);
        DO_STEP(2, 1, 1, srcL);
        DO_STEP(3, 2, 0, srcL);
        DO_STEP(0, 3, 1, srcL);
    }
#undef DO_STEP

    // final hT, cT
    const long offH = (long)T_STEPS * BATCH * F4;
    const long offC = offH + (long)BATCH * F4;
    #pragma unroll
    for (int j = 0; j < 3; j++) {
        out4[offH + (long)b * F4 + tid + 128 * j] = h[j];
        out4[offC + (long)b * F4 + tid + 128 * j] = c[j];
    }
}

extern "C" void kernel_launch(void* const* d_in, const int* in_sizes, int n_in,
                              void* d_out, int out_size)
{
    const float* inputs = (const float*)d_in[0];
    const float* h0     = (const float*)d_in[1];
    const float* c0     = (const float*)d_in[2];
    const float* Wr     = (const float*)d_in[3];
    const float* br     = (const float*)d_in[4];
    const float* Wc     = (const float*)d_in[5];
    const float* bc     = (const float*)d_in[6];
    const float* Wi     = (const float*)d_in[7];
    const float* bi     = (const float*)d_in[8];
    float* out = (float*)d_out;

    fused_kernel<<<BATCH, NTHR>>>(inputs, h0, c0, Wr, br, Wc, bc, Wi, bi, out);
}